// round 3
// baseline (speedup 1.0000x reference)
#include <cuda_runtime.h>
#include <cuda_bf16.h>
#include <math.h>

constexpr int B_   = 2;
constexpr int S_   = 2048;
constexpr int DIM_ = 1024;
constexpr int M_   = B_ * S_;     // 4096
constexpr float SCALE_ = 0.125f;  // 1/sqrt(64)

// Scratch (device globals: allocation-free)
__device__ float g_Q[M_ * 1024];
__device__ float g_K[M_ * 256];
__device__ float g_V[M_ * 256];
__device__ float g_O[M_ * 1024];

// ---------------------------------------------------------------------------
// bf16 helpers
// ---------------------------------------------------------------------------
__device__ __forceinline__ void mma_bf16(float* d, const unsigned* a, const unsigned* b) {
    asm volatile(
        "mma.sync.aligned.m16n8k16.row.col.f32.bf16.bf16.f32 "
        "{%0,%1,%2,%3},{%4,%5,%6,%7},{%8,%9},{%0,%1,%2,%3};\n"
        : "+f"(d[0]), "+f"(d[1]), "+f"(d[2]), "+f"(d[3])
        : "r"(a[0]), "r"(a[1]), "r"(a[2]), "r"(a[3]), "r"(b[0]), "r"(b[1]));
}

__device__ __forceinline__ void split2(float x0, float x1, unsigned& hi, unsigned& lo) {
    __nv_bfloat162 h = __floats2bfloat162_rn(x0, x1);
    float2 hf = __bfloat1622float2(h);
    __nv_bfloat162 l = __floats2bfloat162_rn(x0 - hf.x, x1 - hf.y);
    hi = *reinterpret_cast<unsigned*>(&h);
    lo = *reinterpret_cast<unsigned*>(&l);
}

// ---------------------------------------------------------------------------
// GEMM core (bf16x3 mma): C(128x128) tile, BK=32, 256 thr = 8 warps (2m x 4n),
// warp tile 64x32 = 4x4 m16n8 frags.
// A smem [m][k] bf16 stride 40; B smem [n][k] bf16 stride 40 (conflict-free).
// ---------------------------------------------------------------------------
#define GEMM_SMEM_DECL \
    __shared__ __nv_bfloat16 sAh[128 * 40]; \
    __shared__ __nv_bfloat16 sAl[128 * 40]; \
    __shared__ __nv_bfloat16 sBh[128 * 40]; \
    __shared__ __nv_bfloat16 sBl[128 * 40];

// load A tile (rows m0.., k0..k0+31) from row-major src (ld = 1024)
#define GEMM_LOAD_A(SRC, M0, K0) do { \
    _Pragma("unroll") \
    for (int it = 0; it < 4; it++) { \
        const int idx = tid + it * 256; \
        const int row = idx >> 3; \
        const int kq  = (idx & 7) * 4; \
        float4 v = *(const float4*)&(SRC)[((M0) + row) * 1024 + (K0) + kq]; \
        unsigned h01, l01, h23, l23; \
        split2(v.x, v.y, h01, l01); \
        split2(v.z, v.w, h23, l23); \
        *(uint2*)&sAh[row * 40 + kq] = make_uint2(h01, h23); \
        *(uint2*)&sAl[row * 40 + kq] = make_uint2(l01, l23); \
    } } while (0)

// load B tile (k0..k0+31, cols coff..+127) from row-major W (ld = LDW), store [n][k]
#define GEMM_LOAD_B(W, LDW, COFF, K0) do { \
    _Pragma("unroll") \
    for (int it = 0; it < 4; it++) { \
        const int idx = tid + it * 256; \
        const int k  = idx >> 5; \
        const int n4 = (idx & 31) * 4; \
        float4 v = *(const float4*)&(W)[((K0) + k) * (LDW) + (COFF) + n4]; \
        float vv[4] = {v.x, v.y, v.z, v.w}; \
        _Pragma("unroll") \
        for (int j = 0; j < 4; j++) { \
            __nv_bfloat16 h = __float2bfloat16(vv[j]); \
            float hf = __bfloat162float(h); \
            sBh[(n4 + j) * 40 + k] = h; \
            sBl[(n4 + j) * 40 + k] = __float2bfloat16(vv[j] - hf); \
        } \
    } } while (0)

#define GEMM_MMA_STAGE() do { \
    _Pragma("unroll") \
    for (int ks = 0; ks < 32; ks += 16) { \
        unsigned ah[4][4], al[4][4], bh[4][2], bl[4][2]; \
        _Pragma("unroll") \
        for (int mi = 0; mi < 4; mi++) { \
            const int m = wm * 64 + mi * 16 + lr; \
            ah[mi][0] = *(const unsigned*)&sAh[m * 40 + ks + lc2]; \
            ah[mi][1] = *(const unsigned*)&sAh[(m + 8) * 40 + ks + lc2]; \
            ah[mi][2] = *(const unsigned*)&sAh[m * 40 + ks + lc2 + 8]; \
            ah[mi][3] = *(const unsigned*)&sAh[(m + 8) * 40 + ks + lc2 + 8]; \
            al[mi][0] = *(const unsigned*)&sAl[m * 40 + ks + lc2]; \
            al[mi][1] = *(const unsigned*)&sAl[(m + 8) * 40 + ks + lc2]; \
            al[mi][2] = *(const unsigned*)&sAl[m * 40 + ks + lc2 + 8]; \
            al[mi][3] = *(const unsigned*)&sAl[(m + 8) * 40 + ks + lc2 + 8]; \
        } \
        _Pragma("unroll") \
        for (int ni = 0; ni < 4; ni++) { \
            const int n = wn * 32 + ni * 8 + lr; \
            bh[ni][0] = *(const unsigned*)&sBh[n * 40 + ks + lc2]; \
            bh[ni][1] = *(const unsigned*)&sBh[n * 40 + ks + lc2 + 8]; \
            bl[ni][0] = *(const unsigned*)&sBl[n * 40 + ks + lc2]; \
            bl[ni][1] = *(const unsigned*)&sBl[n * 40 + ks + lc2 + 8]; \
        } \
        _Pragma("unroll") \
        for (int mi = 0; mi < 4; mi++) \
            _Pragma("unroll") \
            for (int ni = 0; ni < 4; ni++) { \
                mma_bf16(acc[mi][ni], ah[mi], bh[ni]); \
                mma_bf16(acc[mi][ni], al[mi], bh[ni]); \
                mma_bf16(acc[mi][ni], ah[mi], bl[ni]); \
            } \
    } } while (0)

// ---------------------------------------------------------------------------
// Kernel 1: QKV projection (bf16x3 mma) + RoPE epilogue.
// ---------------------------------------------------------------------------
__global__ __launch_bounds__(256) void qkv_mma_kernel(
    const float* __restrict__ x,
    const float* __restrict__ wq,
    const float* __restrict__ wk,
    const float* __restrict__ wv,
    const float* __restrict__ cosT,
    const float* __restrict__ sinT)
{
    GEMM_SMEM_DECL

    const int m0 = blockIdx.y * 128;
    const int n0 = blockIdx.x * 128;
    const int tid = threadIdx.x;
    const int warp = tid >> 5;
    const int lane = tid & 31;
    const int wm = warp & 1;
    const int wn = warp >> 1;
    const int lr  = lane >> 2;
    const int lc2 = (lane & 3) * 2;

    const float* w; int ldw, coff;
    if (n0 < 1024)      { w = wq; ldw = 1024; coff = n0; }
    else if (n0 < 1280) { w = wk; ldw = 256;  coff = n0 - 1024; }
    else                { w = wv; ldw = 256;  coff = n0 - 1280; }

    float acc[4][4][4] = {};

    for (int k0 = 0; k0 < DIM_; k0 += 32) {
        GEMM_LOAD_A(x, m0, k0);
        GEMM_LOAD_B(w, ldw, coff, k0);
        __syncthreads();
        GEMM_MMA_STAGE();
        __syncthreads();
    }

    const bool isq = (n0 < 1024);
    const bool isk = (n0 >= 1024 && n0 < 1280);

    #pragma unroll
    for (int mi = 0; mi < 4; mi++) {
        const int row0 = m0 + wm * 64 + mi * 16 + lr;
        #pragma unroll
        for (int ni = 0; ni < 4; ni++) {
            const int col = n0 + wn * 32 + ni * 8 + lc2;
            float e0 = acc[mi][ni][0], o0 = acc[mi][ni][1];   // row0
            float e1 = acc[mi][ni][2], o1 = acc[mi][ni][3];   // row0+8
            if (isq || isk) {
                const int pidx = (col & 63) >> 1;
                const int s0 = row0 & (S_ - 1);
                const int s1 = (row0 + 8) & (S_ - 1);
                float c, sn, re, im;
                c = cosT[s0 * 32 + pidx]; sn = sinT[s0 * 32 + pidx];
                re = e0 * c - o0 * sn; im = e0 * sn + o0 * c; e0 = re; o0 = im;
                c = cosT[s1 * 32 + pidx]; sn = sinT[s1 * 32 + pidx];
                re = e1 * c - o1 * sn; im = e1 * sn + o1 * c; e1 = re; o1 = im;
            }
            if (isq) {
                *(float2*)&g_Q[row0 * 1024 + col]       = make_float2(e0, o0);
                *(float2*)&g_Q[(row0 + 8) * 1024 + col] = make_float2(e1, o1);
            } else if (isk) {
                const int cc = col - 1024;
                *(float2*)&g_K[row0 * 256 + cc]       = make_float2(e0, o0);
                *(float2*)&g_K[(row0 + 8) * 256 + cc] = make_float2(e1, o1);
            } else {
                const int cc = col - 1280;
                *(float2*)&g_V[row0 * 256 + cc]       = make_float2(e0, o0);
                *(float2*)&g_V[(row0 + 8) * 256 + cc] = make_float2(e1, o1);
            }
        }
    }
}

// ---------------------------------------------------------------------------
// Kernel 3: output projection (bf16x3 mma). g_O @ wo -> out.
// ---------------------------------------------------------------------------
__global__ __launch_bounds__(256) void out_mma_kernel(
    const float* __restrict__ wo, float* __restrict__ out)
{
    GEMM_SMEM_DECL

    const int m0 = blockIdx.y * 128;
    const int n0 = blockIdx.x * 128;
    const int tid = threadIdx.x;
    const int warp = tid >> 5;
    const int lane = tid & 31;
    const int wm = warp & 1;
    const int wn = warp >> 1;
    const int lr  = lane >> 2;
    const int lc2 = (lane & 3) * 2;

    float acc[4][4][4] = {};

    for (int k0 = 0; k0 < 1024; k0 += 32) {
        GEMM_LOAD_A(g_O, m0, k0);
        GEMM_LOAD_B(wo, 1024, n0, k0);
        __syncthreads();
        GEMM_MMA_STAGE();
        __syncthreads();
    }

    #pragma unroll
    for (int mi = 0; mi < 4; mi++) {
        const int row0 = m0 + wm * 64 + mi * 16 + lr;
        #pragma unroll
        for (int ni = 0; ni < 4; ni++) {
            const int col = n0 + wn * 32 + ni * 8 + lc2;
            *(float2*)&out[row0 * 1024 + col] =
                make_float2(acc[mi][ni][0], acc[mi][ni][1]);
            *(float2*)&out[(row0 + 8) * 1024 + col] =
                make_float2(acc[mi][ni][2], acc[mi][ni][3]);
        }
    }
}

// ---------------------------------------------------------------------------
// Kernel 2: flash attention (fp32), causal. 128q x 128kv tiles, 8x8 microtile.
// Only the diagonal tile needs masking. Dynamic smem = 169984 B.
// ---------------------------------------------------------------------------
__global__ __launch_bounds__(256) void flash_attn_kernel()
{
    extern __shared__ float sm[];
    float* sQt = sm;                       // [d 64][q 128]  stride 132
    float* sKt = sm + 64 * 132;            // [d 64][kv 128] stride 132
    float* sV  = sm + 2 * 64 * 132;        // [kv 128][d 64] stride 68
    float* sPt = sm + 2 * 64 * 132 + 128 * 68; // [kv 128][q 128] stride 132

    const int qi = blockIdx.x;        // 0..15
    const int h  = blockIdx.y;
    const int b  = blockIdx.z;
    const int g  = h >> 2;
    const int q0 = qi * 128;

    const int tid = threadIdx.x;
    const int tx = tid & 15;
    const int ty = tid >> 4;

    // Q tile transposed
    #pragma unroll
    for (int it = 0; it < 8; it++) {
        const int idx = tid + it * 256;
        const int r  = idx >> 4;
        const int d4 = (idx & 15) * 4;
        float4 qv = *(const float4*)&g_Q[(b * S_ + q0 + r) * 1024 + h * 64 + d4];
        sQt[(d4 + 0) * 132 + r] = qv.x;
        sQt[(d4 + 1) * 132 + r] = qv.y;
        sQt[(d4 + 2) * 132 + r] = qv.z;
        sQt[(d4 + 3) * 132 + r] = qv.w;
    }

    float m_i[8], l_i[8], acc[8][4] = {};
    #pragma unroll
    for (int i = 0; i < 8; i++) { m_i[i] = -INFINITY; l_i[i] = 0.0f; }

    for (int t = 0; t <= qi; t++) {
        const int kv0 = t * 128;
        __syncthreads();

        #pragma unroll
        for (int it = 0; it < 8; it++) {
            const int idx = tid + it * 256;
            const int c  = idx >> 4;
            const int d4 = (idx & 15) * 4;
            float4 kv = *(const float4*)&g_K[(b * S_ + kv0 + c) * 256 + g * 64 + d4];
            sKt[(d4 + 0) * 132 + c] = kv.x;
            sKt[(d4 + 1) * 132 + c] = kv.y;
            sKt[(d4 + 2) * 132 + c] = kv.z;
            sKt[(d4 + 3) * 132 + c] = kv.w;
        }
        #pragma unroll
        for (int it = 0; it < 8; it++) {
            const int idx = tid + it * 256;
            const int k  = idx >> 4;
            const int d4 = (idx & 15) * 4;
            *(float4*)&sV[k * 68 + d4] =
                *(const float4*)&g_V[(b * S_ + kv0 + k) * 256 + g * 64 + d4];
        }
        __syncthreads();

        // S = Q K^T
        float sc[8][8] = {};
        #pragma unroll 4
        for (int kk = 0; kk < 64; kk++) {
            float4 a0 = *(const float4*)&sQt[kk * 132 + ty * 8];
            float4 a1 = *(const float4*)&sQt[kk * 132 + ty * 8 + 4];
            float4 b0 = *(const float4*)&sKt[kk * 132 + tx * 8];
            float4 b1 = *(const float4*)&sKt[kk * 132 + tx * 8 + 4];
            float a[8] = {a0.x,a0.y,a0.z,a0.w,a1.x,a1.y,a1.z,a1.w};
            float bb[8] = {b0.x,b0.y,b0.z,b0.w,b1.x,b1.y,b1.z,b1.w};
            #pragma unroll
            for (int i = 0; i < 8; i++)
                #pragma unroll
                for (int j = 0; j < 8; j++)
                    sc[i][j] += a[i] * bb[j];
        }

        const bool diag = (t == qi);
        #pragma unroll
        for (int i = 0; i < 8; i++) {
            const int rl = ty * 8 + i;
            float p[8];
            float mloc = -INFINITY;
            #pragma unroll
            for (int j = 0; j < 8; j++) {
                float v = sc[i][j] * SCALE_;
                if (diag && (tx * 8 + j > rl)) v = -INFINITY;
                p[j] = v;
                mloc = fmaxf(mloc, v);
            }
            #pragma unroll
            for (int off = 8; off >= 1; off >>= 1)
                mloc = fmaxf(mloc, __shfl_xor_sync(0xffffffffu, mloc, off));

            const float m_new = fmaxf(m_i[i], mloc);
            const float f = __expf(m_i[i] - m_new);
            float lsum = 0.0f;
            #pragma unroll
            for (int j = 0; j < 8; j++) {
                const float e = __expf(p[j] - m_new);
                sPt[(tx * 8 + j) * 132 + rl] = e;
                lsum += e;
            }
            #pragma unroll
            for (int off = 8; off >= 1; off >>= 1)
                lsum += __shfl_xor_sync(0xffffffffu, lsum, off);

            l_i[i] = l_i[i] * f + lsum;
            m_i[i] = m_new;
            #pragma unroll
            for (int j = 0; j < 4; j++) acc[i][j] *= f;
        }
        __syncthreads();

        // O += P @ V
        #pragma unroll 4
        for (int kk = 0; kk < 128; kk++) {
            float4 a0 = *(const float4*)&sPt[kk * 132 + ty * 8];
            float4 a1 = *(const float4*)&sPt[kk * 132 + ty * 8 + 4];
            float4 bv = *(const float4*)&sV[kk * 68 + tx * 4];
            float a[8] = {a0.x,a0.y,a0.z,a0.w,a1.x,a1.y,a1.z,a1.w};
            float bb[4] = {bv.x,bv.y,bv.z,bv.w};
            #pragma unroll
            for (int i = 0; i < 8; i++)
                #pragma unroll
                for (int j = 0; j < 4; j++)
                    acc[i][j] += a[i] * bb[j];
        }
    }

    #pragma unroll
    for (int i = 0; i < 8; i++) {
        const float inv_l = 1.0f / l_i[i];
        const int row = b * S_ + q0 + ty * 8 + i;
        *(float4*)&g_O[row * 1024 + h * 64 + tx * 4] =
            make_float4(acc[i][0] * inv_l, acc[i][1] * inv_l,
                        acc[i][2] * inv_l, acc[i][3] * inv_l);
    }
}

// ---------------------------------------------------------------------------
// inputs: 0=x 1=cos 2=sin 3=mask(unused) 4=wq 5=wk 6=wv 7=wo
// ---------------------------------------------------------------------------
extern "C" void kernel_launch(void* const* d_in, const int* in_sizes, int n_in,
                              void* d_out, int out_size)
{
    const float* x    = (const float*)d_in[0];
    const float* cosT = (const float*)d_in[1];
    const float* sinT = (const float*)d_in[2];
    const float* wq   = (const float*)d_in[4];
    const float* wk   = (const float*)d_in[5];
    const float* wv   = (const float*)d_in[6];
    const float* wo   = (const float*)d_in[7];
    float* out = (float*)d_out;

    constexpr int FLASH_SMEM = (2 * 64 * 132 + 128 * 68 + 128 * 132) * 4; // 169984
    cudaFuncSetAttribute(flash_attn_kernel,
                         cudaFuncAttributeMaxDynamicSharedMemorySize, FLASH_SMEM);

    qkv_mma_kernel<<<dim3(12, 32), 256>>>(x, wq, wk, wv, cosT, sinT);
    flash_attn_kernel<<<dim3(16, 16, 2), 256, FLASH_SMEM>>>();
    out_mma_kernel<<<dim3(8, 32), 256>>>(wo, out);
}

// round 4
// speedup vs baseline: 1.4721x; 1.4721x over previous
#include <cuda_runtime.h>
#include <cuda_bf16.h>
#include <math.h>

constexpr int B_   = 2;
constexpr int S_   = 2048;
constexpr int DIM_ = 1024;
constexpr int M_   = B_ * S_;     // 4096
constexpr float SCALE_ = 0.125f;  // 1/sqrt(64)

// Scratch
__device__ float g_Q[M_ * 1024];
__device__ float g_K[M_ * 256];
__device__ float g_V[M_ * 256];
__device__ float g_O[M_ * 1024];

// ---------------------------------------------------------------------------
// helpers
// ---------------------------------------------------------------------------
__device__ __forceinline__ void mma_bf16(float* d, const unsigned* a, const unsigned* b) {
    asm volatile(
        "mma.sync.aligned.m16n8k16.row.col.f32.bf16.bf16.f32 "
        "{%0,%1,%2,%3},{%4,%5,%6,%7},{%8,%9},{%0,%1,%2,%3};\n"
        : "+f"(d[0]), "+f"(d[1]), "+f"(d[2]), "+f"(d[3])
        : "r"(a[0]), "r"(a[1]), "r"(a[2]), "r"(a[3]), "r"(b[0]), "r"(b[1]));
}

__device__ __forceinline__ void ldsm4(unsigned addr, unsigned* r) {
    asm volatile("ldmatrix.sync.aligned.m8n8.x4.shared.b16 {%0,%1,%2,%3}, [%4];"
                 : "=r"(r[0]), "=r"(r[1]), "=r"(r[2]), "=r"(r[3]) : "r"(addr));
}

__device__ __forceinline__ void split2(float x0, float x1, unsigned& hi, unsigned& lo) {
    __nv_bfloat162 h = __floats2bfloat162_rn(x0, x1);
    float2 hf = __bfloat1622float2(h);
    __nv_bfloat162 l = __floats2bfloat162_rn(x0 - hf.x, x1 - hf.y);
    hi = *reinterpret_cast<unsigned*>(&h);
    lo = *reinterpret_cast<unsigned*>(&l);
}

// ---------------------------------------------------------------------------
// GEMM core: 128x128 tile, BK=32, 8 warps (2m x 4n), warp 64x32.
// A smem [m][k] bf16 stride 40, B smem [n][k] bf16 stride 40, hi/lo pairs.
// Fragments via ldmatrix.x4.
// ---------------------------------------------------------------------------
#define GEMM_SMEM_DECL \
    __shared__ __nv_bfloat16 sAh[128 * 40]; \
    __shared__ __nv_bfloat16 sAl[128 * 40]; \
    __shared__ __nv_bfloat16 sBh[128 * 40]; \
    __shared__ __nv_bfloat16 sBl[128 * 40];

#define GEMM_LOAD_A(SRC, M0, K0) do { \
    _Pragma("unroll") \
    for (int it = 0; it < 4; it++) { \
        const int idx = tid + it * 256; \
        const int row = idx >> 3; \
        const int kq  = (idx & 7) * 4; \
        float4 v = *(const float4*)&(SRC)[((M0) + row) * 1024 + (K0) + kq]; \
        unsigned h01, l01, h23, l23; \
        split2(v.x, v.y, h01, l01); \
        split2(v.z, v.w, h23, l23); \
        *(uint2*)&sAh[row * 40 + kq] = make_uint2(h01, h23); \
        *(uint2*)&sAl[row * 40 + kq] = make_uint2(l01, l23); \
    } } while (0)

#define GEMM_LOAD_B(W, LDW, COFF, K0) do { \
    _Pragma("unroll") \
    for (int it = 0; it < 4; it++) { \
        const int idx = tid + it * 256; \
        const int k  = idx >> 5; \
        const int n4 = (idx & 31) * 4; \
        float4 v = *(const float4*)&(W)[((K0) + k) * (LDW) + (COFF) + n4]; \
        float vv[4] = {v.x, v.y, v.z, v.w}; \
        _Pragma("unroll") \
        for (int j = 0; j < 4; j++) { \
            __nv_bfloat16 h = __float2bfloat16(vv[j]); \
            float hf = __bfloat162float(h); \
            sBh[(n4 + j) * 40 + k] = h; \
            sBl[(n4 + j) * 40 + k] = __float2bfloat16(vv[j] - hf); \
        } \
    } } while (0)

// ldmatrix fragment addresses (bytes within smem arrays)
#define GEMM_MMA_STAGE() do { \
    const unsigned baseAh = (unsigned)__cvta_generic_to_shared(sAh); \
    const unsigned baseAl = (unsigned)__cvta_generic_to_shared(sAl); \
    const unsigned baseBh = (unsigned)__cvta_generic_to_shared(sBh); \
    const unsigned baseBl = (unsigned)__cvta_generic_to_shared(sBl); \
    const int arow = wm * 64 + (lane & 15); \
    const int akof = (lane >> 4) * 8; \
    const int brow = (lane & 7) + ((lane >> 4) & 1) * 8; \
    const int bkof = ((lane >> 3) & 1) * 8; \
    _Pragma("unroll") \
    for (int ks = 0; ks < 32; ks += 16) { \
        unsigned ah[4][4], al[4][4]; \
        _Pragma("unroll") \
        for (int mi = 0; mi < 4; mi++) { \
            const unsigned off = ((arow + mi * 16) * 40 + ks + akof) * 2; \
            ldsm4(baseAh + off, ah[mi]); \
            ldsm4(baseAl + off, al[mi]); \
        } \
        _Pragma("unroll") \
        for (int nip = 0; nip < 2; nip++) { \
            unsigned bh[4], bl[4]; \
            const unsigned off = ((wn * 32 + nip * 16 + brow) * 40 + ks + bkof) * 2; \
            ldsm4(baseBh + off, bh); \
            ldsm4(baseBl + off, bl); \
            _Pragma("unroll") \
            for (int mi = 0; mi < 4; mi++) { \
                mma_bf16(acc[mi][2*nip],   ah[mi], bh); \
                mma_bf16(acc[mi][2*nip],   al[mi], bh); \
                mma_bf16(acc[mi][2*nip],   ah[mi], bl); \
                mma_bf16(acc[mi][2*nip+1], ah[mi], bh + 2); \
                mma_bf16(acc[mi][2*nip+1], al[mi], bh + 2); \
                mma_bf16(acc[mi][2*nip+1], ah[mi], bl + 2); \
            } \
        } \
    } } while (0)

// ---------------------------------------------------------------------------
// Kernel 1: QKV projection + RoPE
// ---------------------------------------------------------------------------
__global__ __launch_bounds__(256) void qkv_mma_kernel(
    const float* __restrict__ x,
    const float* __restrict__ wq,
    const float* __restrict__ wk,
    const float* __restrict__ wv,
    const float* __restrict__ cosT,
    const float* __restrict__ sinT)
{
    GEMM_SMEM_DECL

    const int m0 = blockIdx.y * 128;
    const int n0 = blockIdx.x * 128;
    const int tid = threadIdx.x;
    const int warp = tid >> 5;
    const int lane = tid & 31;
    const int wm = warp & 1;
    const int wn = warp >> 1;
    const int lr  = lane >> 2;
    const int lc2 = (lane & 3) * 2;

    const float* w; int ldw, coff;
    if (n0 < 1024)      { w = wq; ldw = 1024; coff = n0; }
    else if (n0 < 1280) { w = wk; ldw = 256;  coff = n0 - 1024; }
    else                { w = wv; ldw = 256;  coff = n0 - 1280; }

    float acc[4][4][4] = {};

    for (int k0 = 0; k0 < DIM_; k0 += 32) {
        GEMM_LOAD_A(x, m0, k0);
        GEMM_LOAD_B(w, ldw, coff, k0);
        __syncthreads();
        GEMM_MMA_STAGE();
        __syncthreads();
    }

    const bool isq = (n0 < 1024);
    const bool isk = (n0 >= 1024 && n0 < 1280);

    #pragma unroll
    for (int mi = 0; mi < 4; mi++) {
        const int row0 = m0 + wm * 64 + mi * 16 + lr;
        #pragma unroll
        for (int ni = 0; ni < 4; ni++) {
            const int col = n0 + wn * 32 + ni * 8 + lc2;
            float e0 = acc[mi][ni][0], o0 = acc[mi][ni][1];
            float e1 = acc[mi][ni][2], o1 = acc[mi][ni][3];
            if (isq || isk) {
                const int pidx = (col & 63) >> 1;
                const int s0 = row0 & (S_ - 1);
                const int s1 = (row0 + 8) & (S_ - 1);
                float c, sn, re, im;
                c = cosT[s0 * 32 + pidx]; sn = sinT[s0 * 32 + pidx];
                re = e0 * c - o0 * sn; im = e0 * sn + o0 * c; e0 = re; o0 = im;
                c = cosT[s1 * 32 + pidx]; sn = sinT[s1 * 32 + pidx];
                re = e1 * c - o1 * sn; im = e1 * sn + o1 * c; e1 = re; o1 = im;
            }
            if (isq) {
                *(float2*)&g_Q[row0 * 1024 + col]       = make_float2(e0, o0);
                *(float2*)&g_Q[(row0 + 8) * 1024 + col] = make_float2(e1, o1);
            } else if (isk) {
                const int cc = col - 1024;
                *(float2*)&g_K[row0 * 256 + cc]       = make_float2(e0, o0);
                *(float2*)&g_K[(row0 + 8) * 256 + cc] = make_float2(e1, o1);
            } else {
                const int cc = col - 1280;
                *(float2*)&g_V[row0 * 256 + cc]       = make_float2(e0, o0);
                *(float2*)&g_V[(row0 + 8) * 256 + cc] = make_float2(e1, o1);
            }
        }
    }
}

// ---------------------------------------------------------------------------
// Kernel 3: output projection
// ---------------------------------------------------------------------------
__global__ __launch_bounds__(256) void out_mma_kernel(
    const float* __restrict__ wo, float* __restrict__ out)
{
    GEMM_SMEM_DECL

    const int m0 = blockIdx.y * 128;
    const int n0 = blockIdx.x * 128;
    const int tid = threadIdx.x;
    const int warp = tid >> 5;
    const int lane = tid & 31;
    const int wm = warp & 1;
    const int wn = warp >> 1;
    const int lr  = lane >> 2;
    const int lc2 = (lane & 3) * 2;

    float acc[4][4][4] = {};

    for (int k0 = 0; k0 < 1024; k0 += 32) {
        GEMM_LOAD_A(g_O, m0, k0);
        GEMM_LOAD_B(wo, 1024, n0, k0);
        __syncthreads();
        GEMM_MMA_STAGE();
        __syncthreads();
    }

    #pragma unroll
    for (int mi = 0; mi < 4; mi++) {
        const int row0 = m0 + wm * 64 + mi * 16 + lr;
        #pragma unroll
        for (int ni = 0; ni < 4; ni++) {
            const int col = n0 + wn * 32 + ni * 8 + lc2;
            *(float2*)&out[row0 * 1024 + col] =
                make_float2(acc[mi][ni][0], acc[mi][ni][1]);
            *(float2*)&out[(row0 + 8) * 1024 + col] =
                make_float2(acc[mi][ni][2], acc[mi][ni][3]);
        }
    }
}

// ---------------------------------------------------------------------------
// Kernel 2: flash attention on tensor cores (bf16x3), causal.
// 128q x 64kv tiles, 8 warps; warp w owns q rows [w*16, w*16+16).
// Q/K smem [row][d] stride 72; V stored transposed [d][kv] stride 72.
// P stays in registers (accum frags == A frags identity).
// ---------------------------------------------------------------------------
__global__ __launch_bounds__(256) void flash_mma_kernel()
{
    extern __shared__ __nv_bfloat16 smf[];
    __nv_bfloat16* sQh = smf;                 // [128][72]
    __nv_bfloat16* sQl = sQh + 128 * 72;
    __nv_bfloat16* sKh = sQl + 128 * 72;      // [64][72]
    __nv_bfloat16* sKl = sKh + 64 * 72;
    __nv_bfloat16* sVh = sKl + 64 * 72;       // [d=64][kv 72]
    __nv_bfloat16* sVl = sVh + 64 * 72;

    const int qi = blockIdx.x;   // 0..15
    const int h  = blockIdx.y;
    const int b  = blockIdx.z;
    const int g  = h >> 2;
    const int q0 = qi * 128;

    const int tid  = threadIdx.x;
    const int w    = tid >> 5;
    const int lane = tid & 31;
    const int lr   = lane >> 2;
    const int lc2  = (lane & 3) * 2;

    // --- load Q tile (128 x 64), split hi/lo ---
    #pragma unroll
    for (int it = 0; it < 8; it++) {
        const int idx = tid + it * 256;       // 2048 float4
        const int r  = idx >> 4;
        const int d4 = (idx & 15) * 4;
        float4 v = *(const float4*)&g_Q[(b * S_ + q0 + r) * 1024 + h * 64 + d4];
        unsigned h01, l01, h23, l23;
        split2(v.x, v.y, h01, l01);
        split2(v.z, v.w, h23, l23);
        *(uint2*)&sQh[r * 72 + d4] = make_uint2(h01, h23);
        *(uint2*)&sQl[r * 72 + d4] = make_uint2(l01, l23);
    }

    const unsigned baseQh = (unsigned)__cvta_generic_to_shared(sQh);
    const unsigned baseQl = (unsigned)__cvta_generic_to_shared(sQl);
    const unsigned baseKh = (unsigned)__cvta_generic_to_shared(sKh);
    const unsigned baseKl = (unsigned)__cvta_generic_to_shared(sKl);
    const unsigned baseVh = (unsigned)__cvta_generic_to_shared(sVh);
    const unsigned baseVl = (unsigned)__cvta_generic_to_shared(sVl);

    const int arow = w * 16 + (lane & 15);
    const int akof = (lane >> 4) * 8;
    const int brow = (lane & 7) + ((lane >> 4) & 1) * 8;
    const int bkof = ((lane >> 3) & 1) * 8;

    float m0r = -INFINITY, m1r = -INFINITY;   // row maxima (rows lr, lr+8)
    float l0r = 0.0f, l1r = 0.0f;
    float o[8][4] = {};

    const int ntiles = 2 * qi + 2;

    for (int t = 0; t < ntiles; t++) {
        const int kv0 = t * 64;
        __syncthreads();

        // --- load K tile (64 x 64) ---
        #pragma unroll
        for (int it = 0; it < 4; it++) {
            const int idx = tid + it * 256;
            const int c  = idx >> 4;
            const int d4 = (idx & 15) * 4;
            float4 v = *(const float4*)&g_K[(b * S_ + kv0 + c) * 256 + g * 64 + d4];
            unsigned h01, l01, h23, l23;
            split2(v.x, v.y, h01, l01);
            split2(v.z, v.w, h23, l23);
            *(uint2*)&sKh[c * 72 + d4] = make_uint2(h01, h23);
            *(uint2*)&sKl[c * 72 + d4] = make_uint2(l01, l23);
        }
        // --- load V tile transposed: sV[d][kv] ---
        #pragma unroll
        for (int it = 0; it < 4; it++) {
            const int idx = tid + it * 256;
            const int kv = idx >> 4;
            const int d4 = (idx & 15) * 4;
            float4 v = *(const float4*)&g_V[(b * S_ + kv0 + kv) * 256 + g * 64 + d4];
            float vv[4] = {v.x, v.y, v.z, v.w};
            #pragma unroll
            for (int j = 0; j < 4; j++) {
                __nv_bfloat16 hh = __float2bfloat16(vv[j]);
                sVh[(d4 + j) * 72 + kv] = hh;
                sVl[(d4 + j) * 72 + kv] = __float2bfloat16(vv[j] - __bfloat162float(hh));
            }
        }
        __syncthreads();

        if (kv0 > q0 + w * 16 + 15) continue;   // fully masked for this warp

        // --- S = Q K^T (bf16x3) ---
        float s[8][4] = {};
        #pragma unroll
        for (int ks = 0; ks < 64; ks += 16) {
            unsigned ah[4], al[4];
            const unsigned aoff = (arow * 72 + ks + akof) * 2;
            ldsm4(baseQh + aoff, ah);
            ldsm4(baseQl + aoff, al);
            #pragma unroll
            for (int nip = 0; nip < 4; nip++) {
                unsigned bh[4], bl[4];
                const unsigned boff = ((nip * 16 + brow) * 72 + ks + bkof) * 2;
                ldsm4(baseKh + boff, bh);
                ldsm4(baseKl + boff, bl);
                mma_bf16(s[2*nip],   ah, bh);
                mma_bf16(s[2*nip],   al, bh);
                mma_bf16(s[2*nip],   ah, bl);
                mma_bf16(s[2*nip+1], ah, bh + 2);
                mma_bf16(s[2*nip+1], al, bh + 2);
                mma_bf16(s[2*nip+1], ah, bl + 2);
            }
        }

        // --- softmax update ---
        const int r0g = q0 + w * 16 + lr;
        const int r1g = r0g + 8;
        const bool needMask = (kv0 + 63 > q0 + w * 16);

        float mlocA = -INFINITY, mlocB = -INFINITY;
        #pragma unroll
        for (int ni = 0; ni < 8; ni++) {
            #pragma unroll
            for (int j = 0; j < 2; j++) {
                const int col = kv0 + ni * 8 + lc2 + j;
                float v0 = s[ni][j]     * SCALE_;
                float v1 = s[ni][2 + j] * SCALE_;
                if (needMask) {
                    if (col > r0g) v0 = -INFINITY;
                    if (col > r1g) v1 = -INFINITY;
                }
                s[ni][j]     = v0;
                s[ni][2 + j] = v1;
                mlocA = fmaxf(mlocA, v0);
                mlocB = fmaxf(mlocB, v1);
            }
        }
        mlocA = fmaxf(mlocA, __shfl_xor_sync(0xffffffffu, mlocA, 1));
        mlocA = fmaxf(mlocA, __shfl_xor_sync(0xffffffffu, mlocA, 2));
        mlocB = fmaxf(mlocB, __shfl_xor_sync(0xffffffffu, mlocB, 1));
        mlocB = fmaxf(mlocB, __shfl_xor_sync(0xffffffffu, mlocB, 2));

        const float mnA = fmaxf(m0r, mlocA);
        const float mnB = fmaxf(m1r, mlocB);
        const float fA = __expf(m0r - mnA);
        const float fB = __expf(m1r - mnB);
        m0r = mnA; m1r = mnB;

        float lsA = 0.0f, lsB = 0.0f;
        #pragma unroll
        for (int ni = 0; ni < 8; ni++) {
            #pragma unroll
            for (int j = 0; j < 2; j++) {
                float e0 = __expf(s[ni][j]     - mnA);
                float e1 = __expf(s[ni][2 + j] - mnB);
                s[ni][j]     = e0;
                s[ni][2 + j] = e1;
                lsA += e0;
                lsB += e1;
            }
        }
        lsA += __shfl_xor_sync(0xffffffffu, lsA, 1);
        lsA += __shfl_xor_sync(0xffffffffu, lsA, 2);
        lsB += __shfl_xor_sync(0xffffffffu, lsB, 1);
        lsB += __shfl_xor_sync(0xffffffffu, lsB, 2);
        l0r = l0r * fA + lsA;
        l1r = l1r * fB + lsB;

        #pragma unroll
        for (int ni = 0; ni < 8; ni++) {
            o[ni][0] *= fA; o[ni][1] *= fA;
            o[ni][2] *= fB; o[ni][3] *= fB;
        }

        // --- O += P @ V (P from registers, bf16x3) ---
        #pragma unroll
        for (int kc = 0; kc < 4; kc++) {
            unsigned pah[4], pal[4];
            #pragma unroll
            for (int half = 0; half < 2; half++) {
                const int ni = 2 * kc + half;
                split2(s[ni][0], s[ni][1], pah[2*half],     pal[2*half]);
                split2(s[ni][2], s[ni][3], pah[2*half + 1], pal[2*half + 1]);
            }
            #pragma unroll
            for (int nip = 0; nip < 4; nip++) {
                unsigned bvh[4], bvl[4];
                const unsigned boff = ((nip * 16 + brow) * 72 + kc * 16 + bkof) * 2;
                ldsm4(baseVh + boff, bvh);
                ldsm4(baseVl + boff, bvl);
                mma_bf16(o[2*nip],   pah, bvh);
                mma_bf16(o[2*nip],   pal, bvh);
                mma_bf16(o[2*nip],   pah, bvl);
                mma_bf16(o[2*nip+1], pah, bvh + 2);
                mma_bf16(o[2*nip+1], pal, bvh + 2);
                mma_bf16(o[2*nip+1], pah, bvl + 2);
            }
        }
    }

    // --- write O ---
    const float invA = 1.0f / l0r;
    const float invB = 1.0f / l1r;
    const int row0 = b * S_ + q0 + w * 16 + lr;
    #pragma unroll
    for (int ni = 0; ni < 8; ni++) {
        const int col = h * 64 + ni * 8 + lc2;
        *(float2*)&g_O[row0 * 1024 + col] =
            make_float2(o[ni][0] * invA, o[ni][1] * invA);
        *(float2*)&g_O[(row0 + 8) * 1024 + col] =
            make_float2(o[ni][2] * invB, o[ni][3] * invB);
    }
}

// ---------------------------------------------------------------------------
// inputs: 0=x 1=cos 2=sin 3=mask(unused) 4=wq 5=wk 6=wv 7=wo
// ---------------------------------------------------------------------------
extern "C" void kernel_launch(void* const* d_in, const int* in_sizes, int n_in,
                              void* d_out, int out_size)
{
    const float* x    = (const float*)d_in[0];
    const float* cosT = (const float*)d_in[1];
    const float* sinT = (const float*)d_in[2];
    const float* wq   = (const float*)d_in[4];
    const float* wk   = (const float*)d_in[5];
    const float* wv   = (const float*)d_in[6];
    const float* wo   = (const float*)d_in[7];
    float* out = (float*)d_out;

    constexpr int FLASH_SMEM = (2 * 128 * 72 + 4 * 64 * 72) * 2;  // 82944 B
    cudaFuncSetAttribute(flash_mma_kernel,
                         cudaFuncAttributeMaxDynamicSharedMemorySize, FLASH_SMEM);

    qkv_mma_kernel<<<dim3(12, 32), 256>>>(x, wq, wk, wv, cosT, sinT);
    flash_mma_kernel<<<dim3(16, 16, 2), 256, FLASH_SMEM>>>();
    out_mma_kernel<<<dim3(8, 32), 256>>>(wo, out);
}

// round 7
// speedup vs baseline: 2.4630x; 1.6731x over previous
#include <cuda_runtime.h>
#include <cuda_bf16.h>
#include <math.h>

constexpr int B_   = 2;
constexpr int S_   = 2048;
constexpr int M_   = B_ * S_;     // 4096
constexpr float SCALE_ = 0.125f;

// fp32 intermediates for flash
__device__ float g_Q[M_ * 1024];
__device__ float g_K[M_ * 256];
__device__ float g_V[M_ * 256];

// bf16 hi/lo operands
__device__ __nv_bfloat16 g_Xh[M_ * 1024];
__device__ __nv_bfloat16 g_Xl[M_ * 1024];
__device__ __nv_bfloat16 g_WTh[1536 * 1024];   // [n][k] transposed qkv weights
__device__ __nv_bfloat16 g_WTl[1536 * 1024];
__device__ __nv_bfloat16 g_WoTh[1024 * 1024];  // [n][k] transposed wo
__device__ __nv_bfloat16 g_WoTl[1024 * 1024];
__device__ __nv_bfloat16 g_Oh[M_ * 1024];      // attention output hi/lo
__device__ __nv_bfloat16 g_Ol[M_ * 1024];

// ---------------------------------------------------------------------------
// helpers
// ---------------------------------------------------------------------------
__device__ __forceinline__ void mma_bf16(float* d, const unsigned* a, const unsigned* b) {
    asm volatile(
        "mma.sync.aligned.m16n8k16.row.col.f32.bf16.bf16.f32 "
        "{%0,%1,%2,%3},{%4,%5,%6,%7},{%8,%9},{%0,%1,%2,%3};\n"
        : "+f"(d[0]), "+f"(d[1]), "+f"(d[2]), "+f"(d[3])
        : "r"(a[0]), "r"(a[1]), "r"(a[2]), "r"(a[3]), "r"(b[0]), "r"(b[1]));
}
__device__ __forceinline__ void ldsm4(unsigned addr, unsigned* r) {
    asm volatile("ldmatrix.sync.aligned.m8n8.x4.shared.b16 {%0,%1,%2,%3}, [%4];"
                 : "=r"(r[0]), "=r"(r[1]), "=r"(r[2]), "=r"(r[3]) : "r"(addr));
}
__device__ __forceinline__ void split2(float x0, float x1, unsigned& hi, unsigned& lo) {
    __nv_bfloat162 h = __floats2bfloat162_rn(x0, x1);
    float2 hf = __bfloat1622float2(h);
    __nv_bfloat162 l = __floats2bfloat162_rn(x0 - hf.x, x1 - hf.y);
    hi = *reinterpret_cast<unsigned*>(&h);
    lo = *reinterpret_cast<unsigned*>(&l);
}
__device__ __forceinline__ void cpasync16(unsigned dst, const void* src) {
    asm volatile("cp.async.cg.shared.global [%0], [%1], 16;\n" :: "r"(dst), "l"(src));
}

// ---------------------------------------------------------------------------
// conversion kernels
// ---------------------------------------------------------------------------
__global__ __launch_bounds__(256) void convx_kernel(const float* __restrict__ x) {
    const int idx = blockIdx.x * 256 + threadIdx.x;   // float4 index
    float4 v = ((const float4*)x)[idx];
    unsigned h01, l01, h23, l23;
    split2(v.x, v.y, h01, l01);
    split2(v.z, v.w, h23, l23);
    ((uint2*)g_Xh)[idx] = make_uint2(h01, h23);
    ((uint2*)g_Xl)[idx] = make_uint2(l01, l23);
}

// transpose + hi/lo convert: src [1024 x ncols] row-major -> dst[(dstoff+n)][k].
// which = 0 -> g_WT (qkv), which = 1 -> g_WoT. Destination pointers resolved
// in DEVICE code (host-side __device__ symbol addresses are invalid — on GB300
// with ATS they silently write to host memory).
__global__ __launch_bounds__(256) void convw_kernel(
    const float* __restrict__ w, int ncols, int which, int dstoff)
{
    __nv_bfloat16* dsth = which ? g_WoTh : g_WTh;
    __nv_bfloat16* dstl = which ? g_WoTl : g_WTl;

    __shared__ float tile[32][33];
    const int k0 = blockIdx.y * 32;
    const int n0 = blockIdx.x * 32;
    const int tx = threadIdx.x & 31;
    const int ty = threadIdx.x >> 5;
    #pragma unroll
    for (int i = 0; i < 4; i++) {
        const int r = ty + i * 8;
        tile[r][tx] = w[(k0 + r) * ncols + n0 + tx];
    }
    __syncthreads();
    #pragma unroll
    for (int i = 0; i < 4; i++) {
        const int nr = ty + i * 8;
        const float v = tile[tx][nr];
        __nv_bfloat16 h = __float2bfloat16(v);
        const long o = (long)(dstoff + n0 + nr) * 1024 + k0 + tx;
        dsth[o] = h;
        dstl[o] = __float2bfloat16(v - __bfloat162float(h));
    }
}

// ---------------------------------------------------------------------------
// GEMM core: 128x128 tile, BK=64, 3-stage cp.async pipeline, 8 warps (2m x 4n).
// Operands pre-converted bf16 hi/lo, A [m][k] ld=1024, B [n][k] ld=1024.
// Smem per stage: Ah,Al,Bh,Bl each [128][72] bf16. 3 stages = 221184 B.
// ---------------------------------------------------------------------------
constexpr int ST_A_L = 128 * 72;          // elem offsets within a stage
constexpr int ST_B_H = 2 * 128 * 72;
constexpr int ST_B_L = 3 * 128 * 72;
constexpr int STAGE_E = 4 * 128 * 72;     // 36864 elems
constexpr int GEMM_SMEM_B = 3 * STAGE_E * 2;  // 221184 bytes

// 128 rows x 8 k-chunks(8 bf16) = 1024 items; 256 threads x 4 iters.
#define GEMM_LOAD_STAGE(S, K0) do { \
    const int soff = (S) * STAGE_E; \
    _Pragma("unroll") \
    for (int it = 0; it < 4; it++) { \
        const int idx = tid + it * 256; \
        const int row = idx >> 3; \
        const int kq  = (idx & 7) * 8; \
        const unsigned dA = sbase + (soff + row * 72 + kq) * 2; \
        const long aoff = (long)(m0 + row) * 1024 + (K0) + kq; \
        cpasync16(dA,                Ah + aoff); \
        cpasync16(dA + ST_A_L * 2,   Al + aoff); \
        const unsigned dB = sbase + (soff + ST_B_H + row * 72 + kq) * 2; \
        const long boff = (long)(bn0 + row) * 1024 + (K0) + kq; \
        cpasync16(dB,                       Bh + boff); \
        cpasync16(dB + (ST_B_L - ST_B_H) * 2, Bl + boff); \
    } } while (0)

#define GEMM_COMPUTE_STAGE(S) do { \
    const int soff = (S) * STAGE_E; \
    _Pragma("unroll") \
    for (int ks = 0; ks < 64; ks += 16) { \
        unsigned ah[4][4], al[4][4]; \
        _Pragma("unroll") \
        for (int mi = 0; mi < 4; mi++) { \
            const unsigned off = sbase + (soff + (wm * 64 + mi * 16 + (lane & 15)) * 72 + ks + akof) * 2; \
            ldsm4(off, ah[mi]); \
            ldsm4(off + ST_A_L * 2, al[mi]); \
        } \
        _Pragma("unroll") \
        for (int nip = 0; nip < 2; nip++) { \
            unsigned bh[4], bl[4]; \
            const unsigned off = sbase + (soff + ST_B_H + (wn * 32 + nip * 16 + brow) * 72 + ks + bkof) * 2; \
            ldsm4(off, bh); \
            ldsm4(off + (ST_B_L - ST_B_H) * 2, bl); \
            _Pragma("unroll") \
            for (int mi = 0; mi < 4; mi++) { \
                mma_bf16(acc[mi][2*nip],   ah[mi], bh); \
                mma_bf16(acc[mi][2*nip],   al[mi], bh); \
                mma_bf16(acc[mi][2*nip],   ah[mi], bl); \
                mma_bf16(acc[mi][2*nip+1], ah[mi], bh + 2); \
                mma_bf16(acc[mi][2*nip+1], al[mi], bh + 2); \
                mma_bf16(acc[mi][2*nip+1], ah[mi], bl + 2); \
            } \
        } \
    } } while (0)

#define GEMM_MAIN_LOOP() do { \
    GEMM_LOAD_STAGE(0, 0); \
    asm volatile("cp.async.commit_group;\n"); \
    GEMM_LOAD_STAGE(1, 64); \
    asm volatile("cp.async.commit_group;\n"); \
    _Pragma("unroll 1") \
    for (int kt = 0; kt < 16; kt++) { \
        asm volatile("cp.async.wait_group 1;\n"); \
        __syncthreads(); \
        if (kt + 2 < 16) GEMM_LOAD_STAGE((kt + 2) % 3, (kt + 2) * 64); \
        asm volatile("cp.async.commit_group;\n"); \
        GEMM_COMPUTE_STAGE(kt % 3); \
        __syncthreads(); \
    } } while (0)

// ---------------------------------------------------------------------------
// Kernel 1: QKV projection + RoPE
// ---------------------------------------------------------------------------
__global__ __launch_bounds__(256) void qkv_mma_kernel(
    const float* __restrict__ cosT, const float* __restrict__ sinT)
{
    extern __shared__ __nv_bfloat16 smg[];
    const unsigned sbase = (unsigned)__cvta_generic_to_shared(smg);

    const int m0 = blockIdx.y * 128;
    const int n0 = blockIdx.x * 128;
    const int bn0 = n0;
    const int tid = threadIdx.x;
    const int warp = tid >> 5;
    const int lane = tid & 31;
    const int wm = warp & 1;
    const int wn = warp >> 1;
    const int lr  = lane >> 2;
    const int lc2 = (lane & 3) * 2;
    const int akof = (lane >> 4) * 8;
    const int brow = (lane & 7) + ((lane >> 4) & 1) * 8;
    const int bkof = ((lane >> 3) & 1) * 8;

    const __nv_bfloat16* Ah = g_Xh;
    const __nv_bfloat16* Al = g_Xl;
    const __nv_bfloat16* Bh = g_WTh;
    const __nv_bfloat16* Bl = g_WTl;

    float acc[4][4][4] = {};
    GEMM_MAIN_LOOP();

    const bool isq = (n0 < 1024);
    const bool isk = (n0 >= 1024 && n0 < 1280);

    #pragma unroll
    for (int mi = 0; mi < 4; mi++) {
        const int row0 = m0 + wm * 64 + mi * 16 + lr;
        #pragma unroll
        for (int ni = 0; ni < 4; ni++) {
            const int col = n0 + wn * 32 + ni * 8 + lc2;
            float e0 = acc[mi][ni][0], o0 = acc[mi][ni][1];
            float e1 = acc[mi][ni][2], o1 = acc[mi][ni][3];
            if (isq || isk) {
                const int pidx = (col & 63) >> 1;
                const int s0 = row0 & (S_ - 1);
                const int s1 = (row0 + 8) & (S_ - 1);
                float c, sn, re, im;
                c = cosT[s0 * 32 + pidx]; sn = sinT[s0 * 32 + pidx];
                re = e0 * c - o0 * sn; im = e0 * sn + o0 * c; e0 = re; o0 = im;
                c = cosT[s1 * 32 + pidx]; sn = sinT[s1 * 32 + pidx];
                re = e1 * c - o1 * sn; im = e1 * sn + o1 * c; e1 = re; o1 = im;
            }
            if (isq) {
                *(float2*)&g_Q[row0 * 1024 + col]       = make_float2(e0, o0);
                *(float2*)&g_Q[(row0 + 8) * 1024 + col] = make_float2(e1, o1);
            } else if (isk) {
                const int cc = col - 1024;
                *(float2*)&g_K[row0 * 256 + cc]       = make_float2(e0, o0);
                *(float2*)&g_K[(row0 + 8) * 256 + cc] = make_float2(e1, o1);
            } else {
                const int cc = col - 1280;
                *(float2*)&g_V[row0 * 256 + cc]       = make_float2(e0, o0);
                *(float2*)&g_V[(row0 + 8) * 256 + cc] = make_float2(e1, o1);
            }
        }
    }
}

// ---------------------------------------------------------------------------
// Kernel 3: output projection
// ---------------------------------------------------------------------------
__global__ __launch_bounds__(256) void out_mma_kernel(float* __restrict__ out)
{
    extern __shared__ __nv_bfloat16 smg[];
    const unsigned sbase = (unsigned)__cvta_generic_to_shared(smg);

    const int m0 = blockIdx.y * 128;
    const int n0 = blockIdx.x * 128;
    const int bn0 = n0;
    const int tid = threadIdx.x;
    const int warp = tid >> 5;
    const int lane = tid & 31;
    const int wm = warp & 1;
    const int wn = warp >> 1;
    const int lr  = lane >> 2;
    const int lc2 = (lane & 3) * 2;
    const int akof = (lane >> 4) * 8;
    const int brow = (lane & 7) + ((lane >> 4) & 1) * 8;
    const int bkof = ((lane >> 3) & 1) * 8;

    const __nv_bfloat16* Ah = g_Oh;
    const __nv_bfloat16* Al = g_Ol;
    const __nv_bfloat16* Bh = g_WoTh;
    const __nv_bfloat16* Bl = g_WoTl;

    float acc[4][4][4] = {};
    GEMM_MAIN_LOOP();

    #pragma unroll
    for (int mi = 0; mi < 4; mi++) {
        const int row0 = m0 + wm * 64 + mi * 16 + lr;
        #pragma unroll
        for (int ni = 0; ni < 4; ni++) {
            const int col = n0 + wn * 32 + ni * 8 + lc2;
            *(float2*)&out[row0 * 1024 + col] =
                make_float2(acc[mi][ni][0], acc[mi][ni][1]);
            *(float2*)&out[(row0 + 8) * 1024 + col] =
                make_float2(acc[mi][ni][2], acc[mi][ni][3]);
        }
    }
}

// ---------------------------------------------------------------------------
// Kernel 2: flash attention (bf16x3 mma), causal. Writes hi/lo bf16 O.
// ---------------------------------------------------------------------------
__global__ __launch_bounds__(256) void flash_mma_kernel()
{
    extern __shared__ __nv_bfloat16 smf[];
    __nv_bfloat16* sQh = smf;                 // [128][72]
    __nv_bfloat16* sQl = sQh + 128 * 72;
    __nv_bfloat16* sKh = sQl + 128 * 72;      // [64][72]
    __nv_bfloat16* sKl = sKh + 64 * 72;
    __nv_bfloat16* sVh = sKl + 64 * 72;       // [d][kv]
    __nv_bfloat16* sVl = sVh + 64 * 72;

    const int qi = blockIdx.x;
    const int h  = blockIdx.y;
    const int b  = blockIdx.z;
    const int g  = h >> 2;
    const int q0 = qi * 128;

    const int tid  = threadIdx.x;
    const int w    = tid >> 5;
    const int lane = tid & 31;
    const int lr   = lane >> 2;
    const int lc2  = (lane & 3) * 2;

    #pragma unroll
    for (int it = 0; it < 8; it++) {
        const int idx = tid + it * 256;
        const int r  = idx >> 4;
        const int d4 = (idx & 15) * 4;
        float4 v = *(const float4*)&g_Q[(b * S_ + q0 + r) * 1024 + h * 64 + d4];
        unsigned h01, l01, h23, l23;
        split2(v.x, v.y, h01, l01);
        split2(v.z, v.w, h23, l23);
        *(uint2*)&sQh[r * 72 + d4] = make_uint2(h01, h23);
        *(uint2*)&sQl[r * 72 + d4] = make_uint2(l01, l23);
    }

    const unsigned baseQh = (unsigned)__cvta_generic_to_shared(sQh);
    const unsigned baseQl = (unsigned)__cvta_generic_to_shared(sQl);
    const unsigned baseKh = (unsigned)__cvta_generic_to_shared(sKh);
    const unsigned baseKl = (unsigned)__cvta_generic_to_shared(sKl);
    const unsigned baseVh = (unsigned)__cvta_generic_to_shared(sVh);
    const unsigned baseVl = (unsigned)__cvta_generic_to_shared(sVl);

    const int arow = w * 16 + (lane & 15);
    const int akof = (lane >> 4) * 8;
    const int brow = (lane & 7) + ((lane >> 4) & 1) * 8;
    const int bkof = ((lane >> 3) & 1) * 8;

    float m0r = -INFINITY, m1r = -INFINITY;
    float l0r = 0.0f, l1r = 0.0f;
    float o[8][4] = {};

    const int ntiles = 2 * qi + 2;

    for (int t = 0; t < ntiles; t++) {
        const int kv0 = t * 64;
        __syncthreads();

        #pragma unroll
        for (int it = 0; it < 4; it++) {
            const int idx = tid + it * 256;
            const int c  = idx >> 4;
            const int d4 = (idx & 15) * 4;
            float4 v = *(const float4*)&g_K[(b * S_ + kv0 + c) * 256 + g * 64 + d4];
            unsigned h01, l01, h23, l23;
            split2(v.x, v.y, h01, l01);
            split2(v.z, v.w, h23, l23);
            *(uint2*)&sKh[c * 72 + d4] = make_uint2(h01, h23);
            *(uint2*)&sKl[c * 72 + d4] = make_uint2(l01, l23);
        }
        #pragma unroll
        for (int it = 0; it < 4; it++) {
            const int idx = tid + it * 256;
            const int kv = idx >> 4;
            const int d4 = (idx & 15) * 4;
            float4 v = *(const float4*)&g_V[(b * S_ + kv0 + kv) * 256 + g * 64 + d4];
            float vv[4] = {v.x, v.y, v.z, v.w};
            #pragma unroll
            for (int j = 0; j < 4; j++) {
                __nv_bfloat16 hh = __float2bfloat16(vv[j]);
                sVh[(d4 + j) * 72 + kv] = hh;
                sVl[(d4 + j) * 72 + kv] = __float2bfloat16(vv[j] - __bfloat162float(hh));
            }
        }
        __syncthreads();

        if (kv0 > q0 + w * 16 + 15) continue;

        float s[8][4] = {};
        #pragma unroll
        for (int ks = 0; ks < 64; ks += 16) {
            unsigned ah[4], al[4];
            const unsigned aoff = (arow * 72 + ks + akof) * 2;
            ldsm4(baseQh + aoff, ah);
            ldsm4(baseQl + aoff, al);
            #pragma unroll
            for (int nip = 0; nip < 4; nip++) {
                unsigned bh[4], bl[4];
                const unsigned boff = ((nip * 16 + brow) * 72 + ks + bkof) * 2;
                ldsm4(baseKh + boff, bh);
                ldsm4(baseKl + boff, bl);
                mma_bf16(s[2*nip],   ah, bh);
                mma_bf16(s[2*nip],   al, bh);
                mma_bf16(s[2*nip],   ah, bl);
                mma_bf16(s[2*nip+1], ah, bh + 2);
                mma_bf16(s[2*nip+1], al, bh + 2);
                mma_bf16(s[2*nip+1], ah, bl + 2);
            }
        }

        const int r0g = q0 + w * 16 + lr;
        const int r1g = r0g + 8;
        const bool needMask = (kv0 + 63 > q0 + w * 16);

        float mlocA = -INFINITY, mlocB = -INFINITY;
        #pragma unroll
        for (int ni = 0; ni < 8; ni++) {
            #pragma unroll
            for (int j = 0; j < 2; j++) {
                const int col = kv0 + ni * 8 + lc2 + j;
                float v0 = s[ni][j]     * SCALE_;
                float v1 = s[ni][2 + j] * SCALE_;
                if (needMask) {
                    if (col > r0g) v0 = -INFINITY;
                    if (col > r1g) v1 = -INFINITY;
                }
                s[ni][j]     = v0;
                s[ni][2 + j] = v1;
                mlocA = fmaxf(mlocA, v0);
                mlocB = fmaxf(mlocB, v1);
            }
        }
        mlocA = fmaxf(mlocA, __shfl_xor_sync(0xffffffffu, mlocA, 1));
        mlocA = fmaxf(mlocA, __shfl_xor_sync(0xffffffffu, mlocA, 2));
        mlocB = fmaxf(mlocB, __shfl_xor_sync(0xffffffffu, mlocB, 1));
        mlocB = fmaxf(mlocB, __shfl_xor_sync(0xffffffffu, mlocB, 2));

        const float mnA = fmaxf(m0r, mlocA);
        const float mnB = fmaxf(m1r, mlocB);
        const float fA = __expf(m0r - mnA);
        const float fB = __expf(m1r - mnB);
        m0r = mnA; m1r = mnB;

        float lsA = 0.0f, lsB = 0.0f;
        #pragma unroll
        for (int ni = 0; ni < 8; ni++) {
            #pragma unroll
            for (int j = 0; j < 2; j++) {
                float e0 = __expf(s[ni][j]     - mnA);
                float e1 = __expf(s[ni][2 + j] - mnB);
                s[ni][j]     = e0;
                s[ni][2 + j] = e1;
                lsA += e0;
                lsB += e1;
            }
        }
        lsA += __shfl_xor_sync(0xffffffffu, lsA, 1);
        lsA += __shfl_xor_sync(0xffffffffu, lsA, 2);
        lsB += __shfl_xor_sync(0xffffffffu, lsB, 1);
        lsB += __shfl_xor_sync(0xffffffffu, lsB, 2);
        l0r = l0r * fA + lsA;
        l1r = l1r * fB + lsB;

        #pragma unroll
        for (int ni = 0; ni < 8; ni++) {
            o[ni][0] *= fA; o[ni][1] *= fA;
            o[ni][2] *= fB; o[ni][3] *= fB;
        }

        #pragma unroll
        for (int kc = 0; kc < 4; kc++) {
            unsigned pah[4], pal[4];
            #pragma unroll
            for (int half = 0; half < 2; half++) {
                const int ni = 2 * kc + half;
                split2(s[ni][0], s[ni][1], pah[2*half],     pal[2*half]);
                split2(s[ni][2], s[ni][3], pah[2*half + 1], pal[2*half + 1]);
            }
            #pragma unroll
            for (int nip = 0; nip < 4; nip++) {
                unsigned bvh[4], bvl[4];
                const unsigned boff = ((nip * 16 + brow) * 72 + kc * 16 + bkof) * 2;
                ldsm4(baseVh + boff, bvh);
                ldsm4(baseVl + boff, bvl);
                mma_bf16(o[2*nip],   pah, bvh);
                mma_bf16(o[2*nip],   pal, bvh);
                mma_bf16(o[2*nip],   pah, bvl);
                mma_bf16(o[2*nip+1], pah, bvh + 2);
                mma_bf16(o[2*nip+1], pal, bvh + 2);
                mma_bf16(o[2*nip+1], pah, bvl + 2);
            }
        }
    }

    // write O as hi/lo bf16 (feeds out-projection directly)
    const float invA = 1.0f / l0r;
    const float invB = 1.0f / l1r;
    const int row0 = b * S_ + q0 + w * 16 + lr;
    #pragma unroll
    for (int ni = 0; ni < 8; ni++) {
        const int col = h * 64 + ni * 8 + lc2;
        unsigned hA, lA, hB, lB;
        split2(o[ni][0] * invA, o[ni][1] * invA, hA, lA);
        split2(o[ni][2] * invB, o[ni][3] * invB, hB, lB);
        *(unsigned*)&g_Oh[row0 * 1024 + col]       = hA;
        *(unsigned*)&g_Ol[row0 * 1024 + col]       = lA;
        *(unsigned*)&g_Oh[(row0 + 8) * 1024 + col] = hB;
        *(unsigned*)&g_Ol[(row0 + 8) * 1024 + col] = lB;
    }
}

// ---------------------------------------------------------------------------
// inputs: 0=x 1=cos 2=sin 3=mask(unused) 4=wq 5=wk 6=wv 7=wo
// ---------------------------------------------------------------------------
extern "C" void kernel_launch(void* const* d_in, const int* in_sizes, int n_in,
                              void* d_out, int out_size)
{
    const float* x    = (const float*)d_in[0];
    const float* cosT = (const float*)d_in[1];
    const float* sinT = (const float*)d_in[2];
    const float* wq   = (const float*)d_in[4];
    const float* wk   = (const float*)d_in[5];
    const float* wv   = (const float*)d_in[6];
    const float* wo   = (const float*)d_in[7];
    float* out = (float*)d_out;

    constexpr int FLASH_SMEM = (2 * 128 * 72 + 4 * 64 * 72) * 2;  // 82944 B
    cudaFuncSetAttribute(flash_mma_kernel,
                         cudaFuncAttributeMaxDynamicSharedMemorySize, FLASH_SMEM);
    cudaFuncSetAttribute(qkv_mma_kernel,
                         cudaFuncAttributeMaxDynamicSharedMemorySize, GEMM_SMEM_B);
    cudaFuncSetAttribute(out_mma_kernel,
                         cudaFuncAttributeMaxDynamicSharedMemorySize, GEMM_SMEM_B);

    // operand preparation (destinations resolved in device code)
    convx_kernel<<<M_ * 1024 / (256 * 4), 256>>>(x);
    convw_kernel<<<dim3(32, 32), 256>>>(wq, 1024, 0, 0);
    convw_kernel<<<dim3(8,  32), 256>>>(wk, 256,  0, 1024);
    convw_kernel<<<dim3(8,  32), 256>>>(wv, 256,  0, 1280);
    convw_kernel<<<dim3(32, 32), 256>>>(wo, 1024, 1, 0);

    qkv_mma_kernel<<<dim3(12, 32), 256, GEMM_SMEM_B>>>(cosT, sinT);
    flash_mma_kernel<<<dim3(16, 16, 2), 256, FLASH_SMEM>>>();
    out_mma_kernel<<<dim3(8, 32), 256, GEMM_SMEM_B>>>(out);
}

// round 8
// speedup vs baseline: 2.7706x; 1.1249x over previous
#include <cuda_runtime.h>
#include <cuda_bf16.h>
#include <math.h>

constexpr int B_   = 2;
constexpr int S_   = 2048;
constexpr int M_   = B_ * S_;     // 4096
constexpr float SCALE_ = 0.125f;

// bf16 hi/lo operands (all intermediates)
__device__ __nv_bfloat16 g_Xh[M_ * 1024];
__device__ __nv_bfloat16 g_Xl[M_ * 1024];
__device__ __nv_bfloat16 g_WTh[1536 * 1024];   // [n][k] transposed qkv weights
__device__ __nv_bfloat16 g_WTl[1536 * 1024];
__device__ __nv_bfloat16 g_WoTh[1024 * 1024];  // [n][k] transposed wo
__device__ __nv_bfloat16 g_WoTl[1024 * 1024];
__device__ __nv_bfloat16 g_Qh[M_ * 1024];      // rope'd Q hi/lo
__device__ __nv_bfloat16 g_Ql[M_ * 1024];
__device__ __nv_bfloat16 g_Kh[M_ * 256];       // rope'd K hi/lo
__device__ __nv_bfloat16 g_Kl[M_ * 256];
__device__ __nv_bfloat16 g_Vh[M_ * 256];
__device__ __nv_bfloat16 g_Vl[M_ * 256];
__device__ __nv_bfloat16 g_Oh[M_ * 1024];      // attention output hi/lo
__device__ __nv_bfloat16 g_Ol[M_ * 1024];

// ---------------------------------------------------------------------------
// helpers
// ---------------------------------------------------------------------------
__device__ __forceinline__ void mma_bf16(float* d, const unsigned* a, const unsigned* b) {
    asm volatile(
        "mma.sync.aligned.m16n8k16.row.col.f32.bf16.bf16.f32 "
        "{%0,%1,%2,%3},{%4,%5,%6,%7},{%8,%9},{%0,%1,%2,%3};\n"
        : "+f"(d[0]), "+f"(d[1]), "+f"(d[2]), "+f"(d[3])
        : "r"(a[0]), "r"(a[1]), "r"(a[2]), "r"(a[3]), "r"(b[0]), "r"(b[1]));
}
__device__ __forceinline__ void ldsm4(unsigned addr, unsigned* r) {
    asm volatile("ldmatrix.sync.aligned.m8n8.x4.shared.b16 {%0,%1,%2,%3}, [%4];"
                 : "=r"(r[0]), "=r"(r[1]), "=r"(r[2]), "=r"(r[3]) : "r"(addr));
}
__device__ __forceinline__ void ldsm4t(unsigned addr, unsigned* r) {
    asm volatile("ldmatrix.sync.aligned.m8n8.x4.trans.shared.b16 {%0,%1,%2,%3}, [%4];"
                 : "=r"(r[0]), "=r"(r[1]), "=r"(r[2]), "=r"(r[3]) : "r"(addr));
}
__device__ __forceinline__ void split2(float x0, float x1, unsigned& hi, unsigned& lo) {
    __nv_bfloat162 h = __floats2bfloat162_rn(x0, x1);
    float2 hf = __bfloat1622float2(h);
    __nv_bfloat162 l = __floats2bfloat162_rn(x0 - hf.x, x1 - hf.y);
    hi = *reinterpret_cast<unsigned*>(&h);
    lo = *reinterpret_cast<unsigned*>(&l);
}
__device__ __forceinline__ void cpasync16(unsigned dst, const void* src) {
    asm volatile("cp.async.cg.shared.global [%0], [%1], 16;\n" :: "r"(dst), "l"(src));
}

// ---------------------------------------------------------------------------
// conversion kernels
// ---------------------------------------------------------------------------
__global__ __launch_bounds__(256) void convx_kernel(const float* __restrict__ x) {
    const int idx = blockIdx.x * 256 + threadIdx.x;   // float4 index
    float4 v = ((const float4*)x)[idx];
    unsigned h01, l01, h23, l23;
    split2(v.x, v.y, h01, l01);
    split2(v.z, v.w, h23, l23);
    ((uint2*)g_Xh)[idx] = make_uint2(h01, h23);
    ((uint2*)g_Xl)[idx] = make_uint2(l01, l23);
}

// transpose + hi/lo convert; destinations resolved in device code (host-side
// __device__ symbol addresses silently hit host memory via ATS on GB300).
__global__ __launch_bounds__(256) void convw_kernel(
    const float* __restrict__ w, int ncols, int which, int dstoff)
{
    __nv_bfloat16* dsth = which ? g_WoTh : g_WTh;
    __nv_bfloat16* dstl = which ? g_WoTl : g_WTl;

    __shared__ float tile[32][33];
    const int k0 = blockIdx.y * 32;
    const int n0 = blockIdx.x * 32;
    const int tx = threadIdx.x & 31;
    const int ty = threadIdx.x >> 5;
    #pragma unroll
    for (int i = 0; i < 4; i++) {
        const int r = ty + i * 8;
        tile[r][tx] = w[(k0 + r) * ncols + n0 + tx];
    }
    __syncthreads();
    #pragma unroll
    for (int i = 0; i < 4; i++) {
        const int nr = ty + i * 8;
        const float v = tile[tx][nr];
        __nv_bfloat16 h = __float2bfloat16(v);
        const long o = (long)(dstoff + n0 + nr) * 1024 + k0 + tx;
        dsth[o] = h;
        dstl[o] = __float2bfloat16(v - __bfloat162float(h));
    }
}

// ---------------------------------------------------------------------------
// GEMM core: 128x128 tile, BK=64, 3-stage cp.async pipeline, 8 warps (2m x 4n).
// ---------------------------------------------------------------------------
constexpr int ST_A_L = 128 * 72;
constexpr int ST_B_H = 2 * 128 * 72;
constexpr int ST_B_L = 3 * 128 * 72;
constexpr int STAGE_E = 4 * 128 * 72;
constexpr int GEMM_SMEM_B = 3 * STAGE_E * 2;  // 221184 bytes

#define GEMM_LOAD_STAGE(S, K0) do { \
    const int soff = (S) * STAGE_E; \
    _Pragma("unroll") \
    for (int it = 0; it < 4; it++) { \
        const int idx = tid + it * 256; \
        const int row = idx >> 3; \
        const int kq  = (idx & 7) * 8; \
        const unsigned dA = sbase + (soff + row * 72 + kq) * 2; \
        const long aoff = (long)(m0 + row) * 1024 + (K0) + kq; \
        cpasync16(dA,                Ah + aoff); \
        cpasync16(dA + ST_A_L * 2,   Al + aoff); \
        const unsigned dB = sbase + (soff + ST_B_H + row * 72 + kq) * 2; \
        const long boff = (long)(bn0 + row) * 1024 + (K0) + kq; \
        cpasync16(dB,                       Bh + boff); \
        cpasync16(dB + (ST_B_L - ST_B_H) * 2, Bl + boff); \
    } } while (0)

#define GEMM_COMPUTE_STAGE(S) do { \
    const int soff = (S) * STAGE_E; \
    _Pragma("unroll") \
    for (int ks = 0; ks < 64; ks += 16) { \
        unsigned ah[4][4], al[4][4]; \
        _Pragma("unroll") \
        for (int mi = 0; mi < 4; mi++) { \
            const unsigned off = sbase + (soff + (wm * 64 + mi * 16 + (lane & 15)) * 72 + ks + akof) * 2; \
            ldsm4(off, ah[mi]); \
            ldsm4(off + ST_A_L * 2, al[mi]); \
        } \
        _Pragma("unroll") \
        for (int nip = 0; nip < 2; nip++) { \
            unsigned bh[4], bl[4]; \
            const unsigned off = sbase + (soff + ST_B_H + (wn * 32 + nip * 16 + brow) * 72 + ks + bkof) * 2; \
            ldsm4(off, bh); \
            ldsm4(off + (ST_B_L - ST_B_H) * 2, bl); \
            _Pragma("unroll") \
            for (int mi = 0; mi < 4; mi++) { \
                mma_bf16(acc[mi][2*nip],   ah[mi], bh); \
                mma_bf16(acc[mi][2*nip],   al[mi], bh); \
                mma_bf16(acc[mi][2*nip],   ah[mi], bl); \
                mma_bf16(acc[mi][2*nip+1], ah[mi], bh + 2); \
                mma_bf16(acc[mi][2*nip+1], al[mi], bh + 2); \
                mma_bf16(acc[mi][2*nip+1], ah[mi], bl + 2); \
            } \
        } \
    } } while (0)

#define GEMM_MAIN_LOOP() do { \
    GEMM_LOAD_STAGE(0, 0); \
    asm volatile("cp.async.commit_group;\n"); \
    GEMM_LOAD_STAGE(1, 64); \
    asm volatile("cp.async.commit_group;\n"); \
    _Pragma("unroll 1") \
    for (int kt = 0; kt < 16; kt++) { \
        asm volatile("cp.async.wait_group 1;\n"); \
        __syncthreads(); \
        if (kt + 2 < 16) GEMM_LOAD_STAGE((kt + 2) % 3, (kt + 2) * 64); \
        asm volatile("cp.async.commit_group;\n"); \
        GEMM_COMPUTE_STAGE(kt % 3); \
        __syncthreads(); \
    } } while (0)

// ---------------------------------------------------------------------------
// Kernel 1: QKV projection + RoPE; writes Q/K/V as bf16 hi/lo.
// ---------------------------------------------------------------------------
__global__ __launch_bounds__(256) void qkv_mma_kernel(
    const float* __restrict__ cosT, const float* __restrict__ sinT)
{
    extern __shared__ __nv_bfloat16 smg[];
    const unsigned sbase = (unsigned)__cvta_generic_to_shared(smg);

    const int m0 = blockIdx.y * 128;
    const int n0 = blockIdx.x * 128;
    const int bn0 = n0;
    const int tid = threadIdx.x;
    const int warp = tid >> 5;
    const int lane = tid & 31;
    const int wm = warp & 1;
    const int wn = warp >> 1;
    const int lr  = lane >> 2;
    const int lc2 = (lane & 3) * 2;
    const int akof = (lane >> 4) * 8;
    const int brow = (lane & 7) + ((lane >> 4) & 1) * 8;
    const int bkof = ((lane >> 3) & 1) * 8;

    const __nv_bfloat16* Ah = g_Xh;
    const __nv_bfloat16* Al = g_Xl;
    const __nv_bfloat16* Bh = g_WTh;
    const __nv_bfloat16* Bl = g_WTl;

    float acc[4][4][4] = {};
    GEMM_MAIN_LOOP();

    const bool isq = (n0 < 1024);
    const bool isk = (n0 >= 1024 && n0 < 1280);

    #pragma unroll
    for (int mi = 0; mi < 4; mi++) {
        const int row0 = m0 + wm * 64 + mi * 16 + lr;
        #pragma unroll
        for (int ni = 0; ni < 4; ni++) {
            const int col = n0 + wn * 32 + ni * 8 + lc2;
            float e0 = acc[mi][ni][0], o0 = acc[mi][ni][1];
            float e1 = acc[mi][ni][2], o1 = acc[mi][ni][3];
            if (isq || isk) {
                const int pidx = (col & 63) >> 1;
                const int s0 = row0 & (S_ - 1);
                const int s1 = (row0 + 8) & (S_ - 1);
                float c, sn, re, im;
                c = cosT[s0 * 32 + pidx]; sn = sinT[s0 * 32 + pidx];
                re = e0 * c - o0 * sn; im = e0 * sn + o0 * c; e0 = re; o0 = im;
                c = cosT[s1 * 32 + pidx]; sn = sinT[s1 * 32 + pidx];
                re = e1 * c - o1 * sn; im = e1 * sn + o1 * c; e1 = re; o1 = im;
            }
            unsigned h0, l0, h1, l1;
            split2(e0, o0, h0, l0);
            split2(e1, o1, h1, l1);
            if (isq) {
                *(unsigned*)&g_Qh[row0 * 1024 + col]       = h0;
                *(unsigned*)&g_Ql[row0 * 1024 + col]       = l0;
                *(unsigned*)&g_Qh[(row0 + 8) * 1024 + col] = h1;
                *(unsigned*)&g_Ql[(row0 + 8) * 1024 + col] = l1;
            } else if (isk) {
                const int cc = col - 1024;
                *(unsigned*)&g_Kh[row0 * 256 + cc]       = h0;
                *(unsigned*)&g_Kl[row0 * 256 + cc]       = l0;
                *(unsigned*)&g_Kh[(row0 + 8) * 256 + cc] = h1;
                *(unsigned*)&g_Kl[(row0 + 8) * 256 + cc] = l1;
            } else {
                const int cc = col - 1280;
                *(unsigned*)&g_Vh[row0 * 256 + cc]       = h0;
                *(unsigned*)&g_Vl[row0 * 256 + cc]       = l0;
                *(unsigned*)&g_Vh[(row0 + 8) * 256 + cc] = h1;
                *(unsigned*)&g_Vl[(row0 + 8) * 256 + cc] = l1;
            }
        }
    }
}

// ---------------------------------------------------------------------------
// Kernel 3: output projection
// ---------------------------------------------------------------------------
__global__ __launch_bounds__(256) void out_mma_kernel(float* __restrict__ out)
{
    extern __shared__ __nv_bfloat16 smg[];
    const unsigned sbase = (unsigned)__cvta_generic_to_shared(smg);

    const int m0 = blockIdx.y * 128;
    const int n0 = blockIdx.x * 128;
    const int bn0 = n0;
    const int tid = threadIdx.x;
    const int warp = tid >> 5;
    const int lane = tid & 31;
    const int wm = warp & 1;
    const int wn = warp >> 1;
    const int lr  = lane >> 2;
    const int lc2 = (lane & 3) * 2;
    const int akof = (lane >> 4) * 8;
    const int brow = (lane & 7) + ((lane >> 4) & 1) * 8;
    const int bkof = ((lane >> 3) & 1) * 8;

    const __nv_bfloat16* Ah = g_Oh;
    const __nv_bfloat16* Al = g_Ol;
    const __nv_bfloat16* Bh = g_WoTh;
    const __nv_bfloat16* Bl = g_WoTl;

    float acc[4][4][4] = {};
    GEMM_MAIN_LOOP();

    #pragma unroll
    for (int mi = 0; mi < 4; mi++) {
        const int row0 = m0 + wm * 64 + mi * 16 + lr;
        #pragma unroll
        for (int ni = 0; ni < 4; ni++) {
            const int col = n0 + wn * 32 + ni * 8 + lc2;
            *(float2*)&out[row0 * 1024 + col] =
                make_float2(acc[mi][ni][0], acc[mi][ni][1]);
            *(float2*)&out[(row0 + 8) * 1024 + col] =
                make_float2(acc[mi][ni][2], acc[mi][ni][3]);
        }
    }
}

// ---------------------------------------------------------------------------
// Kernel 2: flash attention (bf16x3 mma), causal, cp.async double-buffered
// K/V. V kept row-major [kv][d]; PV B-fragments via ldmatrix.trans.
// smem (bf16 elems): Qh[128*72] Ql[128*72], then 2 stages of
// {Kh,Kl,Vh,Vl}[64*72]. Total 110592 B.
// ---------------------------------------------------------------------------
constexpr int FQE = 128 * 72;
constexpr int FKE = 64 * 72;
constexpr int FSTG0 = 2 * FQE;            // stage 0 base (elems)
constexpr int FSTGSZ = 4 * FKE;           // stage size
constexpr int FLASH_SMEM = (2 * FQE + 2 * FSTGSZ) * 2;  // 110592 B

#define FL_LOAD_TILE(ST, KV0) do { \
    const int sb = FSTG0 + (ST) * FSTGSZ; \
    _Pragma("unroll") \
    for (int it = 0; it < 2; it++) { \
        const int idx = tid + it * 256; \
        const int row = idx >> 3; \
        const int kq  = (idx & 7) * 8; \
        const long gk = (long)(b * S_ + (KV0) + row) * 256 + g * 64 + kq; \
        const unsigned dk = fbase + (sb + row * 72 + kq) * 2; \
        cpasync16(dk,               g_Kh + gk); \
        cpasync16(dk + FKE * 2,     g_Kl + gk); \
        cpasync16(dk + 2 * FKE * 2, g_Vh + gk); \
        cpasync16(dk + 3 * FKE * 2, g_Vl + gk); \
    } } while (0)

__global__ __launch_bounds__(256) void flash_mma_kernel()
{
    extern __shared__ __nv_bfloat16 smf[];
    const unsigned fbase = (unsigned)__cvta_generic_to_shared(smf);

    const int qi = (int)gridDim.x - 1 - (int)blockIdx.x;  // heavy tiles first
    const int h  = blockIdx.y;
    const int b  = blockIdx.z;
    const int g  = h >> 2;
    const int q0 = qi * 128;

    const int tid  = threadIdx.x;
    const int w    = tid >> 5;
    const int lane = tid & 31;
    const int lr   = lane >> 2;
    const int lc2  = (lane & 3) * 2;

    const int arow = w * 16 + (lane & 15);
    const int akof = (lane >> 4) * 8;
    const int brow = (lane & 7) + ((lane >> 4) & 1) * 8;
    const int bkof = ((lane >> 3) & 1) * 8;
    const int vrow = lane & 15;                 // trans-ldsm row (k within tile)
    const int vcof = ((lane >> 4) & 1) * 8;     // trans-ldsm col offset

    // Q tile loads (cp.async, bf16 hi/lo directly from global)
    #pragma unroll
    for (int it = 0; it < 4; it++) {
        const int idx = tid + it * 256;
        const int r  = idx >> 3;
        const int kq = (idx & 7) * 8;
        const long gq = (long)(b * S_ + q0 + r) * 1024 + h * 64 + kq;
        const unsigned dq = fbase + (r * 72 + kq) * 2;
        cpasync16(dq,           g_Qh + gq);
        cpasync16(dq + FQE * 2, g_Ql + gq);
    }
    FL_LOAD_TILE(0, 0);
    asm volatile("cp.async.commit_group;\n");

    float m0r = -INFINITY, m1r = -INFINITY;
    float l0r = 0.0f, l1r = 0.0f;
    float o[8][4] = {};

    const int ntiles = 2 * qi + 2;
    const bool active0 = true;  // all warps active below their diagonal

    #pragma unroll 1
    for (int t = 0; t < ntiles; t++) {
        const int kv0 = t * 64;
        if (t + 1 < ntiles) {
            FL_LOAD_TILE((t + 1) & 1, (t + 1) * 64);
            asm volatile("cp.async.commit_group;\n");
            asm volatile("cp.async.wait_group 1;\n");
        } else {
            asm volatile("cp.async.wait_group 0;\n");
        }
        __syncthreads();

        if (kv0 <= q0 + w * 16 + 15) {
            const int sb = FSTG0 + (t & 1) * FSTGSZ;

            // --- S = Q K^T (bf16x3) ---
            float s[8][4] = {};
            #pragma unroll
            for (int ks = 0; ks < 64; ks += 16) {
                unsigned ah[4], al[4];
                const unsigned aoff = fbase + (arow * 72 + ks + akof) * 2;
                ldsm4(aoff, ah);
                ldsm4(aoff + FQE * 2, al);
                #pragma unroll
                for (int nip = 0; nip < 4; nip++) {
                    unsigned bh[4], bl[4];
                    const unsigned boff = fbase + (sb + (nip * 16 + brow) * 72 + ks + bkof) * 2;
                    ldsm4(boff, bh);
                    ldsm4(boff + FKE * 2, bl);
                    mma_bf16(s[2*nip],   ah, bh);
                    mma_bf16(s[2*nip],   al, bh);
                    mma_bf16(s[2*nip],   ah, bl);
                    mma_bf16(s[2*nip+1], ah, bh + 2);
                    mma_bf16(s[2*nip+1], al, bh + 2);
                    mma_bf16(s[2*nip+1], ah, bl + 2);
                }
            }

            // --- softmax update ---
            const int r0g = q0 + w * 16 + lr;
            const int r1g = r0g + 8;
            const bool needMask = (kv0 + 63 > q0 + w * 16);

            float mlocA = -INFINITY, mlocB = -INFINITY;
            #pragma unroll
            for (int ni = 0; ni < 8; ni++) {
                #pragma unroll
                for (int j = 0; j < 2; j++) {
                    const int col = kv0 + ni * 8 + lc2 + j;
                    float v0 = s[ni][j]     * SCALE_;
                    float v1 = s[ni][2 + j] * SCALE_;
                    if (needMask) {
                        if (col > r0g) v0 = -INFINITY;
                        if (col > r1g) v1 = -INFINITY;
                    }
                    s[ni][j]     = v0;
                    s[ni][2 + j] = v1;
                    mlocA = fmaxf(mlocA, v0);
                    mlocB = fmaxf(mlocB, v1);
                }
            }
            mlocA = fmaxf(mlocA, __shfl_xor_sync(0xffffffffu, mlocA, 1));
            mlocA = fmaxf(mlocA, __shfl_xor_sync(0xffffffffu, mlocA, 2));
            mlocB = fmaxf(mlocB, __shfl_xor_sync(0xffffffffu, mlocB, 1));
            mlocB = fmaxf(mlocB, __shfl_xor_sync(0xffffffffu, mlocB, 2));

            const float mnA = fmaxf(m0r, mlocA);
            const float mnB = fmaxf(m1r, mlocB);
            const float fA = __expf(m0r - mnA);
            const float fB = __expf(m1r - mnB);
            m0r = mnA; m1r = mnB;

            float lsA = 0.0f, lsB = 0.0f;
            #pragma unroll
            for (int ni = 0; ni < 8; ni++) {
                #pragma unroll
                for (int j = 0; j < 2; j++) {
                    float e0 = __expf(s[ni][j]     - mnA);
                    float e1 = __expf(s[ni][2 + j] - mnB);
                    s[ni][j]     = e0;
                    s[ni][2 + j] = e1;
                    lsA += e0;
                    lsB += e1;
                }
            }
            lsA += __shfl_xor_sync(0xffffffffu, lsA, 1);
            lsA += __shfl_xor_sync(0xffffffffu, lsA, 2);
            lsB += __shfl_xor_sync(0xffffffffu, lsB, 1);
            lsB += __shfl_xor_sync(0xffffffffu, lsB, 2);
            l0r = l0r * fA + lsA;
            l1r = l1r * fB + lsB;

            #pragma unroll
            for (int ni = 0; ni < 8; ni++) {
                o[ni][0] *= fA; o[ni][1] *= fA;
                o[ni][2] *= fB; o[ni][3] *= fB;
            }

            // --- O += P @ V : P from registers; V via ldmatrix.trans ---
            #pragma unroll
            for (int kc = 0; kc < 4; kc++) {
                unsigned pah[4], pal[4];
                #pragma unroll
                for (int half = 0; half < 2; half++) {
                    const int ni = 2 * kc + half;
                    split2(s[ni][0], s[ni][1], pah[2*half],     pal[2*half]);
                    split2(s[ni][2], s[ni][3], pah[2*half + 1], pal[2*half + 1]);
                }
                #pragma unroll
                for (int nip = 0; nip < 4; nip++) {
                    unsigned bvh[4], bvl[4];
                    const unsigned voff = fbase +
                        (sb + 2 * FKE + (kc * 16 + vrow) * 72 + nip * 16 + vcof) * 2;
                    ldsm4t(voff, bvh);
                    ldsm4t(voff + FKE * 2, bvl);
                    mma_bf16(o[2*nip],   pah, bvh);
                    mma_bf16(o[2*nip],   pal, bvh);
                    mma_bf16(o[2*nip],   pah, bvl);
                    mma_bf16(o[2*nip+1], pah, bvh + 2);
                    mma_bf16(o[2*nip+1], pal, bvh + 2);
                    mma_bf16(o[2*nip+1], pah, bvl + 2);
                }
            }
        }
        __syncthreads();
    }

    // write O as hi/lo bf16 (feeds out-projection directly)
    const float invA = 1.0f / l0r;
    const float invB = 1.0f / l1r;
    const int row0 = b * S_ + q0 + w * 16 + lr;
    #pragma unroll
    for (int ni = 0; ni < 8; ni++) {
        const int col = h * 64 + ni * 8 + lc2;
        unsigned hA, lA, hB, lB;
        split2(o[ni][0] * invA, o[ni][1] * invA, hA, lA);
        split2(o[ni][2] * invB, o[ni][3] * invB, hB, lB);
        *(unsigned*)&g_Oh[row0 * 1024 + col]       = hA;
        *(unsigned*)&g_Ol[row0 * 1024 + col]       = lA;
        *(unsigned*)&g_Oh[(row0 + 8) * 1024 + col] = hB;
        *(unsigned*)&g_Ol[(row0 + 8) * 1024 + col] = lB;
    }
}

// ---------------------------------------------------------------------------
// inputs: 0=x 1=cos 2=sin 3=mask(unused) 4=wq 5=wk 6=wv 7=wo
// ---------------------------------------------------------------------------
extern "C" void kernel_launch(void* const* d_in, const int* in_sizes, int n_in,
                              void* d_out, int out_size)
{
    const float* x    = (const float*)d_in[0];
    const float* cosT = (const float*)d_in[1];
    const float* sinT = (const float*)d_in[2];
    const float* wq   = (const float*)d_in[4];
    const float* wk   = (const float*)d_in[5];
    const float* wv   = (const float*)d_in[6];
    const float* wo   = (const float*)d_in[7];
    float* out = (float*)d_out;

    cudaFuncSetAttribute(flash_mma_kernel,
                         cudaFuncAttributeMaxDynamicSharedMemorySize, FLASH_SMEM);
    cudaFuncSetAttribute(qkv_mma_kernel,
                         cudaFuncAttributeMaxDynamicSharedMemorySize, GEMM_SMEM_B);
    cudaFuncSetAttribute(out_mma_kernel,
                         cudaFuncAttributeMaxDynamicSharedMemorySize, GEMM_SMEM_B);

    // operand preparation (destinations resolved in device code)
    convx_kernel<<<M_ * 1024 / (256 * 4), 256>>>(x);
    convw_kernel<<<dim3(32, 32), 256>>>(wq, 1024, 0, 0);
    convw_kernel<<<dim3(8,  32), 256>>>(wk, 256,  0, 1024);
    convw_kernel<<<dim3(8,  32), 256>>>(wv, 256,  0, 1280);
    convw_kernel<<<dim3(32, 32), 256>>>(wo, 1024, 1, 0);

    qkv_mma_kernel<<<dim3(12, 32), 256, GEMM_SMEM_B>>>(cosT, sinT);
    flash_mma_kernel<<<dim3(16, 16, 2), 256, FLASH_SMEM>>>();
    out_mma_kernel<<<dim3(8, 32), 256, GEMM_SMEM_B>>>(out);
}

// round 10
// speedup vs baseline: 2.8267x; 1.0203x over previous
#include <cuda_runtime.h>
#include <cuda_bf16.h>
#include <math.h>

constexpr int B_   = 2;
constexpr int S_   = 2048;
constexpr int M_   = B_ * S_;     // 4096
constexpr float SCALE_ = 0.125f;

// bf16 hi/lo operands (all intermediates)
__device__ __nv_bfloat16 g_Xh[M_ * 1024];
__device__ __nv_bfloat16 g_Xl[M_ * 1024];
__device__ __nv_bfloat16 g_WTh[1536 * 1024];   // [n][k] transposed qkv weights
__device__ __nv_bfloat16 g_WTl[1536 * 1024];
__device__ __nv_bfloat16 g_WoTh[1024 * 1024];  // [n][k] transposed wo
__device__ __nv_bfloat16 g_WoTl[1024 * 1024];
__device__ __nv_bfloat16 g_Qh[M_ * 1024];
__device__ __nv_bfloat16 g_Ql[M_ * 1024];
__device__ __nv_bfloat16 g_Kh[M_ * 256];
__device__ __nv_bfloat16 g_Kl[M_ * 256];
__device__ __nv_bfloat16 g_Vh[M_ * 256];
__device__ __nv_bfloat16 g_Vl[M_ * 256];
__device__ __nv_bfloat16 g_Oh[M_ * 1024];
__device__ __nv_bfloat16 g_Ol[M_ * 1024];

// ---------------------------------------------------------------------------
// helpers
// ---------------------------------------------------------------------------
__device__ __forceinline__ void mma_bf16(float* d, const unsigned* a, const unsigned* b) {
    asm volatile(
        "mma.sync.aligned.m16n8k16.row.col.f32.bf16.bf16.f32 "
        "{%0,%1,%2,%3},{%4,%5,%6,%7},{%8,%9},{%0,%1,%2,%3};\n"
        : "+f"(d[0]), "+f"(d[1]), "+f"(d[2]), "+f"(d[3])
        : "r"(a[0]), "r"(a[1]), "r"(a[2]), "r"(a[3]), "r"(b[0]), "r"(b[1]));
}
__device__ __forceinline__ void ldsm4(unsigned addr, unsigned* r) {
    asm volatile("ldmatrix.sync.aligned.m8n8.x4.shared.b16 {%0,%1,%2,%3}, [%4];"
                 : "=r"(r[0]), "=r"(r[1]), "=r"(r[2]), "=r"(r[3]) : "r"(addr));
}
__device__ __forceinline__ void ldsm4t(unsigned addr, unsigned* r) {
    asm volatile("ldmatrix.sync.aligned.m8n8.x4.trans.shared.b16 {%0,%1,%2,%3}, [%4];"
                 : "=r"(r[0]), "=r"(r[1]), "=r"(r[2]), "=r"(r[3]) : "r"(addr));
}
__device__ __forceinline__ void split2(float x0, float x1, unsigned& hi, unsigned& lo) {
    __nv_bfloat162 h = __floats2bfloat162_rn(x0, x1);
    float2 hf = __bfloat1622float2(h);
    __nv_bfloat162 l = __floats2bfloat162_rn(x0 - hf.x, x1 - hf.y);
    hi = *reinterpret_cast<unsigned*>(&h);
    lo = *reinterpret_cast<unsigned*>(&l);
}
__device__ __forceinline__ void cpasync16(unsigned dst, const void* src) {
    asm volatile("cp.async.cg.shared.global [%0], [%1], 16;\n" :: "r"(dst), "l"(src));
}

// ---------------------------------------------------------------------------
// conversion kernels
// ---------------------------------------------------------------------------
__global__ __launch_bounds__(256) void convx_kernel(const float* __restrict__ x) {
    const int idx = blockIdx.x * 256 + threadIdx.x;
    float4 v = ((const float4*)x)[idx];
    unsigned h01, l01, h23, l23;
    split2(v.x, v.y, h01, l01);
    split2(v.z, v.w, h23, l23);
    ((uint2*)g_Xh)[idx] = make_uint2(h01, h23);
    ((uint2*)g_Xl)[idx] = make_uint2(l01, l23);
}

// transpose + hi/lo convert; destinations resolved in device code (host-side
// __device__ symbol addresses silently hit host memory via ATS on GB300).
__global__ __launch_bounds__(256) void convw_kernel(
    const float* __restrict__ w, int ncols, int which, int dstoff)
{
    __nv_bfloat16* dsth = which ? g_WoTh : g_WTh;
    __nv_bfloat16* dstl = which ? g_WoTl : g_WTl;

    __shared__ float tile[32][33];
    const int k0 = blockIdx.y * 32;
    const int n0 = blockIdx.x * 32;
    const int tx = threadIdx.x & 31;
    const int ty = threadIdx.x >> 5;
    #pragma unroll
    for (int i = 0; i < 4; i++) {
        const int r = ty + i * 8;
        tile[r][tx] = w[(k0 + r) * ncols + n0 + tx];
    }
    __syncthreads();
    #pragma unroll
    for (int i = 0; i < 4; i++) {
        const int nr = ty + i * 8;
        const float v = tile[tx][nr];
        __nv_bfloat16 h = __float2bfloat16(v);
        const long o = (long)(dstoff + n0 + nr) * 1024 + k0 + tx;
        dsth[o] = h;
        dstl[o] = __float2bfloat16(v - __bfloat162float(h));
    }
}

// ---------------------------------------------------------------------------
// GEMM core: 128x128 tile, BK=32, 2-stage cp.async double buffer,
// 8 warps (2m x 4n), 2 CTAs/SM. Pitch 40 bf16 (conflict-free ldmatrix).
// Smem: 2 stages x {Ah,Al,Bh,Bl}[128][40] = 81920 B.
// ---------------------------------------------------------------------------
constexpr int ST_A_L = 128 * 40;
constexpr int ST_B_H = 2 * 128 * 40;
constexpr int ST_B_L = 3 * 128 * 40;
constexpr int STAGE_E = 4 * 128 * 40;          // 20480 elems
constexpr int GEMM_SMEM_B = 2 * STAGE_E * 2;   // 81920 bytes

// 128 rows x 4 k-chunks(8 bf16) = 512 items; 256 threads x 2 iters.
#define GEMM_LOAD_STAGE(S, K0) do { \
    const int soff = (S) * STAGE_E; \
    _Pragma("unroll") \
    for (int it = 0; it < 2; it++) { \
        const int idx = tid + it * 256; \
        const int row = idx >> 2; \
        const int kq  = (idx & 3) * 8; \
        const unsigned dA = sbase + (soff + row * 40 + kq) * 2; \
        const long aoff = (long)(m0 + row) * 1024 + (K0) + kq; \
        cpasync16(dA,                Ah + aoff); \
        cpasync16(dA + ST_A_L * 2,   Al + aoff); \
        const unsigned dB = sbase + (soff + ST_B_H + row * 40 + kq) * 2; \
        const long boff = (long)(bn0 + row) * 1024 + (K0) + kq; \
        cpasync16(dB,                         Bh + boff); \
        cpasync16(dB + (ST_B_L - ST_B_H) * 2, Bl + boff); \
    } } while (0)

#define GEMM_COMPUTE_STAGE(S) do { \
    const int soff = (S) * STAGE_E; \
    _Pragma("unroll") \
    for (int ks = 0; ks < 32; ks += 16) { \
        unsigned ah[4][4], al[4][4]; \
        _Pragma("unroll") \
        for (int mi = 0; mi < 4; mi++) { \
            const unsigned off = sbase + (soff + (wm * 64 + mi * 16 + (lane & 15)) * 40 + ks + akof) * 2; \
            ldsm4(off, ah[mi]); \
            ldsm4(off + ST_A_L * 2, al[mi]); \
        } \
        _Pragma("unroll") \
        for (int nip = 0; nip < 2; nip++) { \
            unsigned bh[4], bl[4]; \
            const unsigned off = sbase + (soff + ST_B_H + (wn * 32 + nip * 16 + brow) * 40 + ks + bkof) * 2; \
            ldsm4(off, bh); \
            ldsm4(off + (ST_B_L - ST_B_H) * 2, bl); \
            _Pragma("unroll") \
            for (int mi = 0; mi < 4; mi++) { \
                mma_bf16(acc[mi][2*nip],   ah[mi], bh); \
                mma_bf16(acc[mi][2*nip],   al[mi], bh); \
                mma_bf16(acc[mi][2*nip],   ah[mi], bl); \
                mma_bf16(acc[mi][2*nip+1], ah[mi], bh + 2); \
                mma_bf16(acc[mi][2*nip+1], al[mi], bh + 2); \
                mma_bf16(acc[mi][2*nip+1], ah[mi], bl + 2); \
            } \
        } \
    } } while (0)

#define GEMM_MAIN_LOOP() do { \
    GEMM_LOAD_STAGE(0, 0); \
    asm volatile("cp.async.commit_group;\n"); \
    _Pragma("unroll 1") \
    for (int kt = 0; kt < 32; kt++) { \
        if (kt + 1 < 32) { \
            GEMM_LOAD_STAGE((kt + 1) & 1, (kt + 1) * 32); \
            asm volatile("cp.async.commit_group;\n"); \
            asm volatile("cp.async.wait_group 1;\n"); \
        } else { \
            asm volatile("cp.async.wait_group 0;\n"); \
        } \
        __syncthreads(); \
        GEMM_COMPUTE_STAGE(kt & 1); \
        __syncthreads(); \
    } } while (0)

// ---------------------------------------------------------------------------
// Kernel 1: QKV projection + RoPE; writes Q/K/V as bf16 hi/lo.
// ---------------------------------------------------------------------------
__global__ __launch_bounds__(256, 2) void qkv_mma_kernel(
    const float* __restrict__ cosT, const float* __restrict__ sinT)
{
    extern __shared__ __nv_bfloat16 smg[];
    const unsigned sbase = (unsigned)__cvta_generic_to_shared(smg);

    const int m0 = blockIdx.y * 128;
    const int n0 = blockIdx.x * 128;
    const int bn0 = n0;
    const int tid = threadIdx.x;
    const int warp = tid >> 5;
    const int lane = tid & 31;
    const int wm = warp & 1;
    const int wn = warp >> 1;
    const int lr  = lane >> 2;
    const int lc2 = (lane & 3) * 2;
    const int akof = (lane >> 4) * 8;
    const int brow = (lane & 7) + ((lane >> 4) & 1) * 8;
    const int bkof = ((lane >> 3) & 1) * 8;

    const __nv_bfloat16* Ah = g_Xh;
    const __nv_bfloat16* Al = g_Xl;
    const __nv_bfloat16* Bh = g_WTh;
    const __nv_bfloat16* Bl = g_WTl;

    float acc[4][4][4] = {};
    GEMM_MAIN_LOOP();

    const bool isq = (n0 < 1024);
    const bool isk = (n0 >= 1024 && n0 < 1280);

    #pragma unroll
    for (int mi = 0; mi < 4; mi++) {
        const int row0 = m0 + wm * 64 + mi * 16 + lr;
        #pragma unroll
        for (int ni = 0; ni < 4; ni++) {
            const int col = n0 + wn * 32 + ni * 8 + lc2;
            float e0 = acc[mi][ni][0], o0 = acc[mi][ni][1];
            float e1 = acc[mi][ni][2], o1 = acc[mi][ni][3];
            if (isq || isk) {
                const int pidx = (col & 63) >> 1;
                const int s0 = row0 & (S_ - 1);
                const int s1 = (row0 + 8) & (S_ - 1);
                float c, sn, re, im;
                c = cosT[s0 * 32 + pidx]; sn = sinT[s0 * 32 + pidx];
                re = e0 * c - o0 * sn; im = e0 * sn + o0 * c; e0 = re; o0 = im;
                c = cosT[s1 * 32 + pidx]; sn = sinT[s1 * 32 + pidx];
                re = e1 * c - o1 * sn; im = e1 * sn + o1 * c; e1 = re; o1 = im;
            }
            unsigned h0, l0, h1, l1;
            split2(e0, o0, h0, l0);
            split2(e1, o1, h1, l1);
            if (isq) {
                *(unsigned*)&g_Qh[row0 * 1024 + col]       = h0;
                *(unsigned*)&g_Ql[row0 * 1024 + col]       = l0;
                *(unsigned*)&g_Qh[(row0 + 8) * 1024 + col] = h1;
                *(unsigned*)&g_Ql[(row0 + 8) * 1024 + col] = l1;
            } else if (isk) {
                const int cc = col - 1024;
                *(unsigned*)&g_Kh[row0 * 256 + cc]       = h0;
                *(unsigned*)&g_Kl[row0 * 256 + cc]       = l0;
                *(unsigned*)&g_Kh[(row0 + 8) * 256 + cc] = h1;
                *(unsigned*)&g_Kl[(row0 + 8) * 256 + cc] = l1;
            } else {
                const int cc = col - 1280;
                *(unsigned*)&g_Vh[row0 * 256 + cc]       = h0;
                *(unsigned*)&g_Vl[row0 * 256 + cc]       = l0;
                *(unsigned*)&g_Vh[(row0 + 8) * 256 + cc] = h1;
                *(unsigned*)&g_Vl[(row0 + 8) * 256 + cc] = l1;
            }
        }
    }
}

// ---------------------------------------------------------------------------
// Kernel 3: output projection
// ---------------------------------------------------------------------------
__global__ __launch_bounds__(256, 2) void out_mma_kernel(float* __restrict__ out)
{
    extern __shared__ __nv_bfloat16 smg[];
    const unsigned sbase = (unsigned)__cvta_generic_to_shared(smg);

    const int m0 = blockIdx.y * 128;
    const int n0 = blockIdx.x * 128;
    const int bn0 = n0;
    const int tid = threadIdx.x;
    const int warp = tid >> 5;
    const int lane = tid & 31;
    const int wm = warp & 1;
    const int wn = warp >> 1;
    const int lr  = lane >> 2;
    const int lc2 = (lane & 3) * 2;
    const int akof = (lane >> 4) * 8;
    const int brow = (lane & 7) + ((lane >> 4) & 1) * 8;
    const int bkof = ((lane >> 3) & 1) * 8;

    const __nv_bfloat16* Ah = g_Oh;
    const __nv_bfloat16* Al = g_Ol;
    const __nv_bfloat16* Bh = g_WoTh;
    const __nv_bfloat16* Bl = g_WoTl;

    float acc[4][4][4] = {};
    GEMM_MAIN_LOOP();

    #pragma unroll
    for (int mi = 0; mi < 4; mi++) {
        const int row0 = m0 + wm * 64 + mi * 16 + lr;
        #pragma unroll
        for (int ni = 0; ni < 4; ni++) {
            const int col = n0 + wn * 32 + ni * 8 + lc2;
            *(float2*)&out[row0 * 1024 + col] =
                make_float2(acc[mi][ni][0], acc[mi][ni][1]);
            *(float2*)&out[(row0 + 8) * 1024 + col] =
                make_float2(acc[mi][ni][2], acc[mi][ni][3]);
        }
    }
}

// ---------------------------------------------------------------------------
// Kernel 2: flash attention (bf16x3 mma.sync), causal, cp.async double-buffer,
// 2 CTAs/SM for tensor/softmax overlap.
// ---------------------------------------------------------------------------
constexpr int FQE = 128 * 72;
constexpr int FKE = 64 * 72;
constexpr int FSTG0 = 2 * FQE;
constexpr int FSTGSZ = 4 * FKE;
constexpr int FLASH_SMEM = (2 * FQE + 2 * FSTGSZ) * 2;  // 110592 B

#define FL_LOAD_TILE(ST, KV0) do { \
    const int sb = FSTG0 + (ST) * FSTGSZ; \
    _Pragma("unroll") \
    for (int it = 0; it < 2; it++) { \
        const int idx = tid + it * 256; \
        const int row = idx >> 3; \
        const int kq  = (idx & 7) * 8; \
        const long gk = (long)(b * S_ + (KV0) + row) * 256 + g * 64 + kq; \
        const unsigned dk = fbase + (sb + row * 72 + kq) * 2; \
        cpasync16(dk,               g_Kh + gk); \
        cpasync16(dk + FKE * 2,     g_Kl + gk); \
        cpasync16(dk + 2 * FKE * 2, g_Vh + gk); \
        cpasync16(dk + 3 * FKE * 2, g_Vl + gk); \
    } } while (0)

__global__ __launch_bounds__(256, 2) void flash_mma_kernel()
{
    extern __shared__ __nv_bfloat16 smf[];
    const unsigned fbase = (unsigned)__cvta_generic_to_shared(smf);

    const int qi = (int)gridDim.x - 1 - (int)blockIdx.x;
    const int h  = blockIdx.y;
    const int b  = blockIdx.z;
    const int g  = h >> 2;
    const int q0 = qi * 128;

    const int tid  = threadIdx.x;
    const int w    = tid >> 5;
    const int lane = tid & 31;
    const int lr   = lane >> 2;
    const int lc2  = (lane & 3) * 2;

    const int arow = w * 16 + (lane & 15);
    const int akof = (lane >> 4) * 8;
    const int brow = (lane & 7) + ((lane >> 4) & 1) * 8;
    const int bkof = ((lane >> 3) & 1) * 8;
    const int vrow = lane & 15;
    const int vcof = ((lane >> 4) & 1) * 8;

    #pragma unroll
    for (int it = 0; it < 4; it++) {
        const int idx = tid + it * 256;
        const int r  = idx >> 3;
        const int kq = (idx & 7) * 8;
        const long gq = (long)(b * S_ + q0 + r) * 1024 + h * 64 + kq;
        const unsigned dq = fbase + (r * 72 + kq) * 2;
        cpasync16(dq,           g_Qh + gq);
        cpasync16(dq + FQE * 2, g_Ql + gq);
    }
    FL_LOAD_TILE(0, 0);
    asm volatile("cp.async.commit_group;\n");

    float m0r = -INFINITY, m1r = -INFINITY;
    float l0r = 0.0f, l1r = 0.0f;
    float o[8][4] = {};

    const int ntiles = 2 * qi + 2;

    #pragma unroll 1
    for (int t = 0; t < ntiles; t++) {
        const int kv0 = t * 64;
        if (t + 1 < ntiles) {
            FL_LOAD_TILE((t + 1) & 1, (t + 1) * 64);
            asm volatile("cp.async.commit_group;\n");
            asm volatile("cp.async.wait_group 1;\n");
        } else {
            asm volatile("cp.async.wait_group 0;\n");
        }
        __syncthreads();

        if (kv0 <= q0 + w * 16 + 15) {
            const int sb = FSTG0 + (t & 1) * FSTGSZ;

            float s[8][4] = {};
            #pragma unroll
            for (int ks = 0; ks < 64; ks += 16) {
                unsigned ah[4], al[4];
                const unsigned aoff = fbase + (arow * 72 + ks + akof) * 2;
                ldsm4(aoff, ah);
                ldsm4(aoff + FQE * 2, al);
                #pragma unroll
                for (int nip = 0; nip < 4; nip++) {
                    unsigned bh[4], bl[4];
                    const unsigned boff = fbase + (sb + (nip * 16 + brow) * 72 + ks + bkof) * 2;
                    ldsm4(boff, bh);
                    ldsm4(boff + FKE * 2, bl);
                    mma_bf16(s[2*nip],   ah, bh);
                    mma_bf16(s[2*nip],   al, bh);
                    mma_bf16(s[2*nip],   ah, bl);
                    mma_bf16(s[2*nip+1], ah, bh + 2);
                    mma_bf16(s[2*nip+1], al, bh + 2);
                    mma_bf16(s[2*nip+1], ah, bl + 2);
                }
            }

            const int r0g = q0 + w * 16 + lr;
            const int r1g = r0g + 8;
            const bool needMask = (kv0 + 63 > q0 + w * 16);

            float mlocA = -INFINITY, mlocB = -INFINITY;
            #pragma unroll
            for (int ni = 0; ni < 8; ni++) {
                #pragma unroll
                for (int j = 0; j < 2; j++) {
                    const int col = kv0 + ni * 8 + lc2 + j;
                    float v0 = s[ni][j]     * SCALE_;
                    float v1 = s[ni][2 + j] * SCALE_;
                    if (needMask) {
                        if (col > r0g) v0 = -INFINITY;
                        if (col > r1g) v1 = -INFINITY;
                    }
                    s[ni][j]     = v0;
                    s[ni][2 + j] = v1;
                    mlocA = fmaxf(mlocA, v0);
                    mlocB = fmaxf(mlocB, v1);
                }
            }
            mlocA = fmaxf(mlocA, __shfl_xor_sync(0xffffffffu, mlocA, 1));
            mlocA = fmaxf(mlocA, __shfl_xor_sync(0xffffffffu, mlocA, 2));
            mlocB = fmaxf(mlocB, __shfl_xor_sync(0xffffffffu, mlocB, 1));
            mlocB = fmaxf(mlocB, __shfl_xor_sync(0xffffffffu, mlocB, 2));

            const float mnA = fmaxf(m0r, mlocA);
            const float mnB = fmaxf(m1r, mlocB);
            const float fA = __expf(m0r - mnA);
            const float fB = __expf(m1r - mnB);
            m0r = mnA; m1r = mnB;

            float lsA = 0.0f, lsB = 0.0f;
            #pragma unroll
            for (int ni = 0; ni < 8; ni++) {
                #pragma unroll
                for (int j = 0; j < 2; j++) {
                    float e0 = __expf(s[ni][j]     - mnA);
                    float e1 = __expf(s[ni][2 + j] - mnB);
                    s[ni][j]     = e0;
                    s[ni][2 + j] = e1;
                    lsA += e0;
                    lsB += e1;
                }
            }
            lsA += __shfl_xor_sync(0xffffffffu, lsA, 1);
            lsA += __shfl_xor_sync(0xffffffffu, lsA, 2);
            lsB += __shfl_xor_sync(0xffffffffu, lsB, 1);
            lsB += __shfl_xor_sync(0xffffffffu, lsB, 2);
            l0r = l0r * fA + lsA;
            l1r = l1r * fB + lsB;

            #pragma unroll
            for (int ni = 0; ni < 8; ni++) {
                o[ni][0] *= fA; o[ni][1] *= fA;
                o[ni][2] *= fB; o[ni][3] *= fB;
            }

            #pragma unroll
            for (int kc = 0; kc < 4; kc++) {
                unsigned pah[4], pal[4];
                #pragma unroll
                for (int half = 0; half < 2; half++) {
                    const int ni = 2 * kc + half;
                    split2(s[ni][0], s[ni][1], pah[2*half],     pal[2*half]);
                    split2(s[ni][2], s[ni][3], pah[2*half + 1], pal[2*half + 1]);
                }
                #pragma unroll
                for (int nip = 0; nip < 4; nip++) {
                    unsigned bvh[4], bvl[4];
                    const unsigned voff = fbase +
                        (sb + 2 * FKE + (kc * 16 + vrow) * 72 + nip * 16 + vcof) * 2;
                    ldsm4t(voff, bvh);
                    ldsm4t(voff + FKE * 2, bvl);
                    mma_bf16(o[2*nip],   pah, bvh);
                    mma_bf16(o[2*nip],   pal, bvh);
                    mma_bf16(o[2*nip],   pah, bvl);
                    mma_bf16(o[2*nip+1], pah, bvh + 2);
                    mma_bf16(o[2*nip+1], pal, bvh + 2);
                    mma_bf16(o[2*nip+1], pah, bvl + 2);
                }
            }
        }
        __syncthreads();
    }

    const float invA = 1.0f / l0r;
    const float invB = 1.0f / l1r;
    const int row0 = b * S_ + q0 + w * 16 + lr;
    #pragma unroll
    for (int ni = 0; ni < 8; ni++) {
        const int col = h * 64 + ni * 8 + lc2;
        unsigned hA, lA, hB, lB;
        split2(o[ni][0] * invA, o[ni][1] * invA, hA, lA);
        split2(o[ni][2] * invB, o[ni][3] * invB, hB, lB);
        *(unsigned*)&g_Oh[row0 * 1024 + col]       = hA;
        *(unsigned*)&g_Ol[row0 * 1024 + col]       = lA;
        *(unsigned*)&g_Oh[(row0 + 8) * 1024 + col] = hB;
        *(unsigned*)&g_Ol[(row0 + 8) * 1024 + col] = lB;
    }
}

// ---------------------------------------------------------------------------
// inputs: 0=x 1=cos 2=sin 3=mask(unused) 4=wq 5=wk 6=wv 7=wo
// ---------------------------------------------------------------------------
extern "C" void kernel_launch(void* const* d_in, const int* in_sizes, int n_in,
                              void* d_out, int out_size)
{
    const float* x    = (const float*)d_in[0];
    const float* cosT = (const float*)d_in[1];
    const float* sinT = (const float*)d_in[2];
    const float* wq   = (const float*)d_in[4];
    const float* wk   = (const float*)d_in[5];
    const float* wv   = (const float*)d_in[6];
    const float* wo   = (const float*)d_in[7];
    float* out = (float*)d_out;

    cudaFuncSetAttribute(flash_mma_kernel,
                         cudaFuncAttributeMaxDynamicSharedMemorySize, FLASH_SMEM);
    cudaFuncSetAttribute(qkv_mma_kernel,
                         cudaFuncAttributeMaxDynamicSharedMemorySize, GEMM_SMEM_B);
    cudaFuncSetAttribute(out_mma_kernel,
                         cudaFuncAttributeMaxDynamicSharedMemorySize, GEMM_SMEM_B);

    convx_kernel<<<M_ * 1024 / (256 * 4), 256>>>(x);
    convw_kernel<<<dim3(32, 32), 256>>>(wq, 1024, 0, 0);
    convw_kernel<<<dim3(8,  32), 256>>>(wk, 256,  0, 1024);
    convw_kernel<<<dim3(8,  32), 256>>>(wv, 256,  0, 1280);
    convw_kernel<<<dim3(32, 32), 256>>>(wo, 1024, 1, 0);

    qkv_mma_kernel<<<dim3(12, 32), 256, GEMM_SMEM_B>>>(cosT, sinT);
    flash_mma_kernel<<<dim3(16, 16, 2), 256, FLASH_SMEM>>>();
    out_mma_kernel<<<dim3(8, 32), 256, GEMM_SMEM_B>>>(out);
}

// round 11
// speedup vs baseline: 3.0746x; 1.0877x over previous
#include <cuda_runtime.h>
#include <cuda_bf16.h>
#include <math.h>

constexpr int B_   = 2;
constexpr int S_   = 2048;
constexpr int M_   = B_ * S_;     // 4096
constexpr float SCALE_ = 0.125f;

// bf16 hi/lo operands (all intermediates)
__device__ __nv_bfloat16 g_Xh[M_ * 1024];
__device__ __nv_bfloat16 g_Xl[M_ * 1024];
__device__ __nv_bfloat16 g_WTh[1536 * 1024];   // [n][k] transposed qkv weights
__device__ __nv_bfloat16 g_WTl[1536 * 1024];
__device__ __nv_bfloat16 g_WoTh[1024 * 1024];  // [n][k] transposed wo
__device__ __nv_bfloat16 g_WoTl[1024 * 1024];
__device__ __nv_bfloat16 g_Qh[M_ * 1024];
__device__ __nv_bfloat16 g_Ql[M_ * 1024];
__device__ __nv_bfloat16 g_Kh[M_ * 256];       // K hi only (2-term QK^T)
__device__ __nv_bfloat16 g_Vh[M_ * 256];
__device__ __nv_bfloat16 g_Vl[M_ * 256];
__device__ __nv_bfloat16 g_Oh[M_ * 1024];
__device__ __nv_bfloat16 g_Ol[M_ * 1024];

// ---------------------------------------------------------------------------
// helpers
// ---------------------------------------------------------------------------
__device__ __forceinline__ void mma_bf16(float* d, const unsigned* a, const unsigned* b) {
    asm volatile(
        "mma.sync.aligned.m16n8k16.row.col.f32.bf16.bf16.f32 "
        "{%0,%1,%2,%3},{%4,%5,%6,%7},{%8,%9},{%0,%1,%2,%3};\n"
        : "+f"(d[0]), "+f"(d[1]), "+f"(d[2]), "+f"(d[3])
        : "r"(a[0]), "r"(a[1]), "r"(a[2]), "r"(a[3]), "r"(b[0]), "r"(b[1]));
}
__device__ __forceinline__ void ldsm4(unsigned addr, unsigned* r) {
    asm volatile("ldmatrix.sync.aligned.m8n8.x4.shared.b16 {%0,%1,%2,%3}, [%4];"
                 : "=r"(r[0]), "=r"(r[1]), "=r"(r[2]), "=r"(r[3]) : "r"(addr));
}
__device__ __forceinline__ void ldsm4t(unsigned addr, unsigned* r) {
    asm volatile("ldmatrix.sync.aligned.m8n8.x4.trans.shared.b16 {%0,%1,%2,%3}, [%4];"
                 : "=r"(r[0]), "=r"(r[1]), "=r"(r[2]), "=r"(r[3]) : "r"(addr));
}
__device__ __forceinline__ void split2(float x0, float x1, unsigned& hi, unsigned& lo) {
    __nv_bfloat162 h = __floats2bfloat162_rn(x0, x1);
    float2 hf = __bfloat1622float2(h);
    __nv_bfloat162 l = __floats2bfloat162_rn(x0 - hf.x, x1 - hf.y);
    hi = *reinterpret_cast<unsigned*>(&h);
    lo = *reinterpret_cast<unsigned*>(&l);
}
__device__ __forceinline__ void cpasync16(unsigned dst, const void* src) {
    asm volatile("cp.async.cg.shared.global [%0], [%1], 16;\n" :: "r"(dst), "l"(src));
}

// ---------------------------------------------------------------------------
// conversion kernels
// ---------------------------------------------------------------------------
__global__ __launch_bounds__(256) void convx_kernel(const float* __restrict__ x) {
    const int idx = blockIdx.x * 256 + threadIdx.x;
    float4 v = ((const float4*)x)[idx];
    unsigned h01, l01, h23, l23;
    split2(v.x, v.y, h01, l01);
    split2(v.z, v.w, h23, l23);
    ((uint2*)g_Xh)[idx] = make_uint2(h01, h23);
    ((uint2*)g_Xl)[idx] = make_uint2(l01, l23);
}

// All four weight transposes in ONE launch. Region select on blockIdx.x.
// Destinations resolved in device code (host-side __device__ symbol addresses
// silently hit host memory via ATS on GB300).
__global__ __launch_bounds__(256) void convw_all_kernel(
    const float* __restrict__ wq, const float* __restrict__ wk,
    const float* __restrict__ wv, const float* __restrict__ wo)
{
    int bx = blockIdx.x;
    const float* w; int ncols, dstoff;
    __nv_bfloat16 *dsth, *dstl;
    if (bx < 32)      { w = wq; ncols = 1024; dstoff = 0;    dsth = g_WTh;  dstl = g_WTl; }
    else if (bx < 40) { w = wk; ncols = 256;  dstoff = 1024; dsth = g_WTh;  dstl = g_WTl;  bx -= 32; }
    else if (bx < 48) { w = wv; ncols = 256;  dstoff = 1280; dsth = g_WTh;  dstl = g_WTl;  bx -= 40; }
    else              { w = wo; ncols = 1024; dstoff = 0;    dsth = g_WoTh; dstl = g_WoTl; bx -= 48; }

    __shared__ float tile[32][33];
    const int k0 = blockIdx.y * 32;
    const int n0 = bx * 32;
    const int tx = threadIdx.x & 31;
    const int ty = threadIdx.x >> 5;
    #pragma unroll
    for (int i = 0; i < 4; i++) {
        const int r = ty + i * 8;
        tile[r][tx] = w[(k0 + r) * ncols + n0 + tx];
    }
    __syncthreads();
    #pragma unroll
    for (int i = 0; i < 4; i++) {
        const int nr = ty + i * 8;
        const float v = tile[tx][nr];
        __nv_bfloat16 h = __float2bfloat16(v);
        const long o = (long)(dstoff + n0 + nr) * 1024 + k0 + tx;
        dsth[o] = h;
        dstl[o] = __float2bfloat16(v - __bfloat162float(h));
    }
}

// ---------------------------------------------------------------------------
// GEMM core: 128x128 tile, BK=32, 2-stage cp.async double buffer,
// 8 warps (2m x 4n), 2 CTAs/SM. Pitch 40 bf16 (conflict-free ldmatrix).
// ---------------------------------------------------------------------------
constexpr int ST_A_L = 128 * 40;
constexpr int ST_B_H = 2 * 128 * 40;
constexpr int ST_B_L = 3 * 128 * 40;
constexpr int STAGE_E = 4 * 128 * 40;
constexpr int GEMM_SMEM_B = 2 * STAGE_E * 2;   // 81920 bytes

#define GEMM_LOAD_STAGE(S, K0) do { \
    const int soff = (S) * STAGE_E; \
    _Pragma("unroll") \
    for (int it = 0; it < 2; it++) { \
        const int idx = tid + it * 256; \
        const int row = idx >> 2; \
        const int kq  = (idx & 3) * 8; \
        const unsigned dA = sbase + (soff + row * 40 + kq) * 2; \
        const long aoff = (long)(m0 + row) * 1024 + (K0) + kq; \
        cpasync16(dA,                Ah + aoff); \
        cpasync16(dA + ST_A_L * 2,   Al + aoff); \
        const unsigned dB = sbase + (soff + ST_B_H + row * 40 + kq) * 2; \
        const long boff = (long)(bn0 + row) * 1024 + (K0) + kq; \
        cpasync16(dB,                         Bh + boff); \
        cpasync16(dB + (ST_B_L - ST_B_H) * 2, Bl + boff); \
    } } while (0)

#define GEMM_COMPUTE_STAGE(S) do { \
    const int soff = (S) * STAGE_E; \
    _Pragma("unroll") \
    for (int ks = 0; ks < 32; ks += 16) { \
        unsigned ah[4][4], al[4][4]; \
        _Pragma("unroll") \
        for (int mi = 0; mi < 4; mi++) { \
            const unsigned off = sbase + (soff + (wm * 64 + mi * 16 + (lane & 15)) * 40 + ks + akof) * 2; \
            ldsm4(off, ah[mi]); \
            ldsm4(off + ST_A_L * 2, al[mi]); \
        } \
        _Pragma("unroll") \
        for (int nip = 0; nip < 2; nip++) { \
            unsigned bh[4], bl[4]; \
            const unsigned off = sbase + (soff + ST_B_H + (wn * 32 + nip * 16 + brow) * 40 + ks + bkof) * 2; \
            ldsm4(off, bh); \
            ldsm4(off + (ST_B_L - ST_B_H) * 2, bl); \
            _Pragma("unroll") \
            for (int mi = 0; mi < 4; mi++) { \
                mma_bf16(acc[mi][2*nip],   ah[mi], bh); \
                mma_bf16(acc[mi][2*nip],   al[mi], bh); \
                mma_bf16(acc[mi][2*nip],   ah[mi], bl); \
                mma_bf16(acc[mi][2*nip+1], ah[mi], bh + 2); \
                mma_bf16(acc[mi][2*nip+1], al[mi], bh + 2); \
                mma_bf16(acc[mi][2*nip+1], ah[mi], bl + 2); \
            } \
        } \
    } } while (0)

#define GEMM_MAIN_LOOP() do { \
    GEMM_LOAD_STAGE(0, 0); \
    asm volatile("cp.async.commit_group;\n"); \
    _Pragma("unroll 1") \
    for (int kt = 0; kt < 32; kt++) { \
        if (kt + 1 < 32) { \
            GEMM_LOAD_STAGE((kt + 1) & 1, (kt + 1) * 32); \
            asm volatile("cp.async.commit_group;\n"); \
            asm volatile("cp.async.wait_group 1;\n"); \
        } else { \
            asm volatile("cp.async.wait_group 0;\n"); \
        } \
        __syncthreads(); \
        GEMM_COMPUTE_STAGE(kt & 1); \
        __syncthreads(); \
    } } while (0)

// ---------------------------------------------------------------------------
// Kernel 1: QKV projection + RoPE; writes Q hi/lo, K hi, V hi/lo.
// ---------------------------------------------------------------------------
__global__ __launch_bounds__(256, 2) void qkv_mma_kernel(
    const float* __restrict__ cosT, const float* __restrict__ sinT)
{
    extern __shared__ __nv_bfloat16 smg[];
    const unsigned sbase = (unsigned)__cvta_generic_to_shared(smg);

    const int m0 = blockIdx.y * 128;
    const int n0 = blockIdx.x * 128;
    const int bn0 = n0;
    const int tid = threadIdx.x;
    const int warp = tid >> 5;
    const int lane = tid & 31;
    const int wm = warp & 1;
    const int wn = warp >> 1;
    const int lr  = lane >> 2;
    const int lc2 = (lane & 3) * 2;
    const int akof = (lane >> 4) * 8;
    const int brow = (lane & 7) + ((lane >> 4) & 1) * 8;
    const int bkof = ((lane >> 3) & 1) * 8;

    const __nv_bfloat16* Ah = g_Xh;
    const __nv_bfloat16* Al = g_Xl;
    const __nv_bfloat16* Bh = g_WTh;
    const __nv_bfloat16* Bl = g_WTl;

    float acc[4][4][4] = {};
    GEMM_MAIN_LOOP();

    const bool isq = (n0 < 1024);
    const bool isk = (n0 >= 1024 && n0 < 1280);

    #pragma unroll
    for (int mi = 0; mi < 4; mi++) {
        const int row0 = m0 + wm * 64 + mi * 16 + lr;
        #pragma unroll
        for (int ni = 0; ni < 4; ni++) {
            const int col = n0 + wn * 32 + ni * 8 + lc2;
            float e0 = acc[mi][ni][0], o0 = acc[mi][ni][1];
            float e1 = acc[mi][ni][2], o1 = acc[mi][ni][3];
            if (isq || isk) {
                const int pidx = (col & 63) >> 1;
                const int s0 = row0 & (S_ - 1);
                const int s1 = (row0 + 8) & (S_ - 1);
                float c, sn, re, im;
                c = cosT[s0 * 32 + pidx]; sn = sinT[s0 * 32 + pidx];
                re = e0 * c - o0 * sn; im = e0 * sn + o0 * c; e0 = re; o0 = im;
                c = cosT[s1 * 32 + pidx]; sn = sinT[s1 * 32 + pidx];
                re = e1 * c - o1 * sn; im = e1 * sn + o1 * c; e1 = re; o1 = im;
            }
            unsigned h0, l0, h1, l1;
            split2(e0, o0, h0, l0);
            split2(e1, o1, h1, l1);
            if (isq) {
                *(unsigned*)&g_Qh[row0 * 1024 + col]       = h0;
                *(unsigned*)&g_Ql[row0 * 1024 + col]       = l0;
                *(unsigned*)&g_Qh[(row0 + 8) * 1024 + col] = h1;
                *(unsigned*)&g_Ql[(row0 + 8) * 1024 + col] = l1;
            } else if (isk) {
                const int cc = col - 1024;
                *(unsigned*)&g_Kh[row0 * 256 + cc]       = h0;   // hi only
                *(unsigned*)&g_Kh[(row0 + 8) * 256 + cc] = h1;
            } else {
                const int cc = col - 1280;
                *(unsigned*)&g_Vh[row0 * 256 + cc]       = h0;
                *(unsigned*)&g_Vl[row0 * 256 + cc]       = l0;
                *(unsigned*)&g_Vh[(row0 + 8) * 256 + cc] = h1;
                *(unsigned*)&g_Vl[(row0 + 8) * 256 + cc] = l1;
            }
        }
    }
}

// ---------------------------------------------------------------------------
// Kernel 3: output projection
// ---------------------------------------------------------------------------
__global__ __launch_bounds__(256, 2) void out_mma_kernel(float* __restrict__ out)
{
    extern __shared__ __nv_bfloat16 smg[];
    const unsigned sbase = (unsigned)__cvta_generic_to_shared(smg);

    const int m0 = blockIdx.y * 128;
    const int n0 = blockIdx.x * 128;
    const int bn0 = n0;
    const int tid = threadIdx.x;
    const int warp = tid >> 5;
    const int lane = tid & 31;
    const int wm = warp & 1;
    const int wn = warp >> 1;
    const int lr  = lane >> 2;
    const int lc2 = (lane & 3) * 2;
    const int akof = (lane >> 4) * 8;
    const int brow = (lane & 7) + ((lane >> 4) & 1) * 8;
    const int bkof = ((lane >> 3) & 1) * 8;

    const __nv_bfloat16* Ah = g_Oh;
    const __nv_bfloat16* Al = g_Ol;
    const __nv_bfloat16* Bh = g_WoTh;
    const __nv_bfloat16* Bl = g_WoTl;

    float acc[4][4][4] = {};
    GEMM_MAIN_LOOP();

    #pragma unroll
    for (int mi = 0; mi < 4; mi++) {
        const int row0 = m0 + wm * 64 + mi * 16 + lr;
        #pragma unroll
        for (int ni = 0; ni < 4; ni++) {
            const int col = n0 + wn * 32 + ni * 8 + lc2;
            *(float2*)&out[row0 * 1024 + col] =
                make_float2(acc[mi][ni][0], acc[mi][ni][1]);
            *(float2*)&out[(row0 + 8) * 1024 + col] =
                make_float2(acc[mi][ni][2], acc[mi][ni][3]);
        }
    }
}

// ---------------------------------------------------------------------------
// Kernel 2: flash attention, causal, cp.async double-buffer, 2 CTAs/SM.
// QK^T is 2-term (QhKh + QlKh); K-lo eliminated. PV stays 3-term.
// smem: Qh[128*72], Ql[128*72], 2 stages of {Kh,Vh,Vl}[64*72]. 92160 B.
// ---------------------------------------------------------------------------
constexpr int FQE = 128 * 72;
constexpr int FKE = 64 * 72;
constexpr int FSTG0 = 2 * FQE;
constexpr int FSTGSZ = 3 * FKE;
constexpr int FLASH_SMEM = (2 * FQE + 2 * FSTGSZ) * 2;  // 92160 B

#define FL_LOAD_TILE(ST, KV0) do { \
    const int sb = FSTG0 + (ST) * FSTGSZ; \
    _Pragma("unroll") \
    for (int it = 0; it < 2; it++) { \
        const int idx = tid + it * 256; \
        const int row = idx >> 3; \
        const int kq  = (idx & 7) * 8; \
        const long gk = (long)(b * S_ + (KV0) + row) * 256 + g * 64 + kq; \
        const unsigned dk = fbase + (sb + row * 72 + kq) * 2; \
        cpasync16(dk,               g_Kh + gk); \
        cpasync16(dk + FKE * 2,     g_Vh + gk); \
        cpasync16(dk + 2 * FKE * 2, g_Vl + gk); \
    } } while (0)

__global__ __launch_bounds__(256, 2) void flash_mma_kernel()
{
    extern __shared__ __nv_bfloat16 smf[];
    const unsigned fbase = (unsigned)__cvta_generic_to_shared(smf);

    const int qi = (int)gridDim.x - 1 - (int)blockIdx.x;
    const int h  = blockIdx.y;
    const int b  = blockIdx.z;
    const int g  = h >> 2;
    const int q0 = qi * 128;

    const int tid  = threadIdx.x;
    const int w    = tid >> 5;
    const int lane = tid & 31;
    const int lr   = lane >> 2;
    const int lc2  = (lane & 3) * 2;

    const int arow = w * 16 + (lane & 15);
    const int akof = (lane >> 4) * 8;
    const int brow = (lane & 7) + ((lane >> 4) & 1) * 8;
    const int bkof = ((lane >> 3) & 1) * 8;
    const int vrow = lane & 15;
    const int vcof = ((lane >> 4) & 1) * 8;

    #pragma unroll
    for (int it = 0; it < 4; it++) {
        const int idx = tid + it * 256;
        const int r  = idx >> 3;
        const int kq = (idx & 7) * 8;
        const long gq = (long)(b * S_ + q0 + r) * 1024 + h * 64 + kq;
        const unsigned dq = fbase + (r * 72 + kq) * 2;
        cpasync16(dq,           g_Qh + gq);
        cpasync16(dq + FQE * 2, g_Ql + gq);
    }
    FL_LOAD_TILE(0, 0);
    asm volatile("cp.async.commit_group;\n");

    float m0r = -INFINITY, m1r = -INFINITY;
    float l0r = 0.0f, l1r = 0.0f;
    float o[8][4] = {};

    const int ntiles = 2 * qi + 2;

    #pragma unroll 1
    for (int t = 0; t < ntiles; t++) {
        const int kv0 = t * 64;
        if (t + 1 < ntiles) {
            FL_LOAD_TILE((t + 1) & 1, (t + 1) * 64);
            asm volatile("cp.async.commit_group;\n");
            asm volatile("cp.async.wait_group 1;\n");
        } else {
            asm volatile("cp.async.wait_group 0;\n");
        }
        __syncthreads();

        if (kv0 <= q0 + w * 16 + 15) {
            const int sb = FSTG0 + (t & 1) * FSTGSZ;

            // --- S = Q K^T : 2-term bf16 (QhKh + QlKh) ---
            float s[8][4] = {};
            #pragma unroll
            for (int ks = 0; ks < 64; ks += 16) {
                unsigned ah[4], al[4];
                const unsigned aoff = fbase + (arow * 72 + ks + akof) * 2;
                ldsm4(aoff, ah);
                ldsm4(aoff + FQE * 2, al);
                #pragma unroll
                for (int nip = 0; nip < 4; nip++) {
                    unsigned bh[4];
                    const unsigned boff = fbase + (sb + (nip * 16 + brow) * 72 + ks + bkof) * 2;
                    ldsm4(boff, bh);
                    mma_bf16(s[2*nip],   ah, bh);
                    mma_bf16(s[2*nip],   al, bh);
                    mma_bf16(s[2*nip+1], ah, bh + 2);
                    mma_bf16(s[2*nip+1], al, bh + 2);
                }
            }

            const int r0g = q0 + w * 16 + lr;
            const int r1g = r0g + 8;
            const bool needMask = (kv0 + 63 > q0 + w * 16);

            float mlocA = -INFINITY, mlocB = -INFINITY;
            #pragma unroll
            for (int ni = 0; ni < 8; ni++) {
                #pragma unroll
                for (int j = 0; j < 2; j++) {
                    const int col = kv0 + ni * 8 + lc2 + j;
                    float v0 = s[ni][j]     * SCALE_;
                    float v1 = s[ni][2 + j] * SCALE_;
                    if (needMask) {
                        if (col > r0g) v0 = -INFINITY;
                        if (col > r1g) v1 = -INFINITY;
                    }
                    s[ni][j]     = v0;
                    s[ni][2 + j] = v1;
                    mlocA = fmaxf(mlocA, v0);
                    mlocB = fmaxf(mlocB, v1);
                }
            }
            mlocA = fmaxf(mlocA, __shfl_xor_sync(0xffffffffu, mlocA, 1));
            mlocA = fmaxf(mlocA, __shfl_xor_sync(0xffffffffu, mlocA, 2));
            mlocB = fmaxf(mlocB, __shfl_xor_sync(0xffffffffu, mlocB, 1));
            mlocB = fmaxf(mlocB, __shfl_xor_sync(0xffffffffu, mlocB, 2));

            const float mnA = fmaxf(m0r, mlocA);
            const float mnB = fmaxf(m1r, mlocB);
            const float fA = __expf(m0r - mnA);
            const float fB = __expf(m1r - mnB);
            m0r = mnA; m1r = mnB;

            float lsA = 0.0f, lsB = 0.0f;
            #pragma unroll
            for (int ni = 0; ni < 8; ni++) {
                #pragma unroll
                for (int j = 0; j < 2; j++) {
                    float e0 = __expf(s[ni][j]     - mnA);
                    float e1 = __expf(s[ni][2 + j] - mnB);
                    s[ni][j]     = e0;
                    s[ni][2 + j] = e1;
                    lsA += e0;
                    lsB += e1;
                }
            }
            lsA += __shfl_xor_sync(0xffffffffu, lsA, 1);
            lsA += __shfl_xor_sync(0xffffffffu, lsA, 2);
            lsB += __shfl_xor_sync(0xffffffffu, lsB, 1);
            lsB += __shfl_xor_sync(0xffffffffu, lsB, 2);
            l0r = l0r * fA + lsA;
            l1r = l1r * fB + lsB;

            #pragma unroll
            for (int ni = 0; ni < 8; ni++) {
                o[ni][0] *= fA; o[ni][1] *= fA;
                o[ni][2] *= fB; o[ni][3] *= fB;
            }

            // --- O += P @ V : 3-term (PhVh + PlVh + PhVl) ---
            #pragma unroll
            for (int kc = 0; kc < 4; kc++) {
                unsigned pah[4], pal[4];
                #pragma unroll
                for (int half = 0; half < 2; half++) {
                    const int ni = 2 * kc + half;
                    split2(s[ni][0], s[ni][1], pah[2*half],     pal[2*half]);
                    split2(s[ni][2], s[ni][3], pah[2*half + 1], pal[2*half + 1]);
                }
                #pragma unroll
                for (int nip = 0; nip < 4; nip++) {
                    unsigned bvh[4], bvl[4];
                    const unsigned voff = fbase +
                        (sb + FKE + (kc * 16 + vrow) * 72 + nip * 16 + vcof) * 2;
                    ldsm4t(voff, bvh);
                    ldsm4t(voff + FKE * 2, bvl);
                    mma_bf16(o[2*nip],   pah, bvh);
                    mma_bf16(o[2*nip],   pal, bvh);
                    mma_bf16(o[2*nip],   pah, bvl);
                    mma_bf16(o[2*nip+1], pah, bvh + 2);
                    mma_bf16(o[2*nip+1], pal, bvh + 2);
                    mma_bf16(o[2*nip+1], pah, bvl + 2);
                }
            }
        }
        __syncthreads();
    }

    const float invA = 1.0f / l0r;
    const float invB = 1.0f / l1r;
    const int row0 = b * S_ + q0 + w * 16 + lr;
    #pragma unroll
    for (int ni = 0; ni < 8; ni++) {
        const int col = h * 64 + ni * 8 + lc2;
        unsigned hA, lA, hB, lB;
        split2(o[ni][0] * invA, o[ni][1] * invA, hA, lA);
        split2(o[ni][2] * invB, o[ni][3] * invB, hB, lB);
        *(unsigned*)&g_Oh[row0 * 1024 + col]       = hA;
        *(unsigned*)&g_Ol[row0 * 1024 + col]       = lA;
        *(unsigned*)&g_Oh[(row0 + 8) * 1024 + col] = hB;
        *(unsigned*)&g_Ol[(row0 + 8) * 1024 + col] = lB;
    }
}

// ---------------------------------------------------------------------------
// inputs: 0=x 1=cos 2=sin 3=mask(unused) 4=wq 5=wk 6=wv 7=wo
// ---------------------------------------------------------------------------
extern "C" void kernel_launch(void* const* d_in, const int* in_sizes, int n_in,
                              void* d_out, int out_size)
{
    const float* x    = (const float*)d_in[0];
    const float* cosT = (const float*)d_in[1];
    const float* sinT = (const float*)d_in[2];
    const float* wq   = (const float*)d_in[4];
    const float* wk   = (const float*)d_in[5];
    const float* wv   = (const float*)d_in[6];
    const float* wo   = (const float*)d_in[7];
    float* out = (float*)d_out;

    cudaFuncSetAttribute(flash_mma_kernel,
                         cudaFuncAttributeMaxDynamicSharedMemorySize, FLASH_SMEM);
    cudaFuncSetAttribute(qkv_mma_kernel,
                         cudaFuncAttributeMaxDynamicSharedMemorySize, GEMM_SMEM_B);
    cudaFuncSetAttribute(out_mma_kernel,
                         cudaFuncAttributeMaxDynamicSharedMemorySize, GEMM_SMEM_B);

    convx_kernel<<<M_ * 1024 / (256 * 4), 256>>>(x);
    convw_all_kernel<<<dim3(80, 32), 256>>>(wq, wk, wv, wo);

    qkv_mma_kernel<<<dim3(12, 32), 256, GEMM_SMEM_B>>>(cosT, sinT);
    flash_mma_kernel<<<dim3(16, 16, 2), 256, FLASH_SMEM>>>();
    out_mma_kernel<<<dim3(8, 32), 256, GEMM_SMEM_B>>>(out);
}

// round 13
// speedup vs baseline: 3.2016x; 1.0413x over previous
#include <cuda_runtime.h>
#include <cuda_bf16.h>
#include <math.h>

constexpr int B_   = 2;
constexpr int S_   = 2048;
constexpr int M_   = B_ * S_;     // 4096
// softmax scale folded into Q: 0.125 * log2(e); flash uses exp2
constexpr float QSCALE_ = 0.125f * 1.44269504088896f;

// bf16 hi/lo operands (all intermediates)
__device__ __nv_bfloat16 g_Xh[M_ * 1024];
__device__ __nv_bfloat16 g_Xl[M_ * 1024];
__device__ __nv_bfloat16 g_WTh[1536 * 1024];   // [n][k] transposed qkv weights
__device__ __nv_bfloat16 g_WTl[1536 * 1024];
__device__ __nv_bfloat16 g_WoTh[1024 * 1024];  // [n][k] transposed wo
__device__ __nv_bfloat16 g_WoTl[1024 * 1024];
__device__ __nv_bfloat16 g_Qh[M_ * 1024];      // pre-scaled by QSCALE_
__device__ __nv_bfloat16 g_Ql[M_ * 1024];
__device__ __nv_bfloat16 g_Kh[M_ * 256];       // K hi only (2-term QK^T)
__device__ __nv_bfloat16 g_Vh[M_ * 256];
__device__ __nv_bfloat16 g_Vl[M_ * 256];
__device__ __nv_bfloat16 g_Oh[M_ * 1024];
__device__ __nv_bfloat16 g_Ol[M_ * 1024];

// ---------------------------------------------------------------------------
// helpers
// ---------------------------------------------------------------------------
__device__ __forceinline__ void mma_bf16(float* d, const unsigned* a, const unsigned* b) {
    asm volatile(
        "mma.sync.aligned.m16n8k16.row.col.f32.bf16.bf16.f32 "
        "{%0,%1,%2,%3},{%4,%5,%6,%7},{%8,%9},{%0,%1,%2,%3};\n"
        : "+f"(d[0]), "+f"(d[1]), "+f"(d[2]), "+f"(d[3])
        : "r"(a[0]), "r"(a[1]), "r"(a[2]), "r"(a[3]), "r"(b[0]), "r"(b[1]));
}
__device__ __forceinline__ void ldsm4(unsigned addr, unsigned* r) {
    asm volatile("ldmatrix.sync.aligned.m8n8.x4.shared.b16 {%0,%1,%2,%3}, [%4];"
                 : "=r"(r[0]), "=r"(r[1]), "=r"(r[2]), "=r"(r[3]) : "r"(addr));
}
__device__ __forceinline__ void ldsm4t(unsigned addr, unsigned* r) {
    asm volatile("ldmatrix.sync.aligned.m8n8.x4.trans.shared.b16 {%0,%1,%2,%3}, [%4];"
                 : "=r"(r[0]), "=r"(r[1]), "=r"(r[2]), "=r"(r[3]) : "r"(addr));
}
__device__ __forceinline__ void split2(float x0, float x1, unsigned& hi, unsigned& lo) {
    __nv_bfloat162 h = __floats2bfloat162_rn(x0, x1);
    float2 hf = __bfloat1622float2(h);
    __nv_bfloat162 l = __floats2bfloat162_rn(x0 - hf.x, x1 - hf.y);
    hi = *reinterpret_cast<unsigned*>(&h);
    lo = *reinterpret_cast<unsigned*>(&l);
}
__device__ __forceinline__ void cpasync16(unsigned dst, const void* src) {
    asm volatile("cp.async.cg.shared.global [%0], [%1], 16;\n" :: "r"(dst), "l"(src));
}
__device__ __forceinline__ float ex2_fast(float x) {
    float r;
    asm("ex2.approx.ftz.f32 %0, %1;" : "=f"(r) : "f"(x));
    return r;
}

// ---------------------------------------------------------------------------
// conversion kernels
// ---------------------------------------------------------------------------
__global__ __launch_bounds__(256) void convx_kernel(const float* __restrict__ x) {
    const int idx = blockIdx.x * 256 + threadIdx.x;
    float4 v = ((const float4*)x)[idx];
    unsigned h01, l01, h23, l23;
    split2(v.x, v.y, h01, l01);
    split2(v.z, v.w, h23, l23);
    ((uint2*)g_Xh)[idx] = make_uint2(h01, h23);
    ((uint2*)g_Xl)[idx] = make_uint2(l01, l23);
}

// All four weight transposes in ONE launch. Destinations resolved in device
// code (host-side __device__ symbol addresses silently hit host memory via ATS).
__global__ __launch_bounds__(256) void convw_all_kernel(
    const float* __restrict__ wq, const float* __restrict__ wk,
    const float* __restrict__ wv, const float* __restrict__ wo)
{
    int bx = blockIdx.x;
    const float* w; int ncols, dstoff;
    __nv_bfloat16 *dsth, *dstl;
    if (bx < 32)      { w = wq; ncols = 1024; dstoff = 0;    dsth = g_WTh;  dstl = g_WTl; }
    else if (bx < 40) { w = wk; ncols = 256;  dstoff = 1024; dsth = g_WTh;  dstl = g_WTl;  bx -= 32; }
    else if (bx < 48) { w = wv; ncols = 256;  dstoff = 1280; dsth = g_WTh;  dstl = g_WTl;  bx -= 40; }
    else              { w = wo; ncols = 1024; dstoff = 0;    dsth = g_WoTh; dstl = g_WoTl; bx -= 48; }

    __shared__ float tile[32][33];
    const int k0 = blockIdx.y * 32;
    const int n0 = bx * 32;
    const int tx = threadIdx.x & 31;
    const int ty = threadIdx.x >> 5;
    #pragma unroll
    for (int i = 0; i < 4; i++) {
        const int r = ty + i * 8;
        tile[r][tx] = w[(k0 + r) * ncols + n0 + tx];
    }
    __syncthreads();
    #pragma unroll
    for (int i = 0; i < 4; i++) {
        const int nr = ty + i * 8;
        const float v = tile[tx][nr];
        __nv_bfloat16 h = __float2bfloat16(v);
        const long o = (long)(dstoff + n0 + nr) * 1024 + k0 + tx;
        dsth[o] = h;
        dstl[o] = __float2bfloat16(v - __bfloat162float(h));
    }
}

// ---------------------------------------------------------------------------
// GEMM core: 128x128 tile, BK=32, double buffer, 8 warps, 2 CTAs/SM.
// SINGLE sync per iteration: wait(t) -> sync -> issue loads(t+1) -> compute(t).
// ---------------------------------------------------------------------------
constexpr int ST_A_L = 128 * 40;
constexpr int ST_B_H = 2 * 128 * 40;
constexpr int ST_B_L = 3 * 128 * 40;
constexpr int STAGE_E = 4 * 128 * 40;
constexpr int GEMM_SMEM_B = 2 * STAGE_E * 2;   // 81920 bytes

#define GEMM_LOAD_STAGE(S, K0) do { \
    const int soff = (S) * STAGE_E; \
    _Pragma("unroll") \
    for (int it = 0; it < 2; it++) { \
        const int idx = tid + it * 256; \
        const int row = idx >> 2; \
        const int kq  = (idx & 3) * 8; \
        const unsigned dA = sbase + (soff + row * 40 + kq) * 2; \
        const long aoff = (long)(m0 + row) * 1024 + (K0) + kq; \
        cpasync16(dA,                Ah + aoff); \
        cpasync16(dA + ST_A_L * 2,   Al + aoff); \
        const unsigned dB = sbase + (soff + ST_B_H + row * 40 + kq) * 2; \
        const long boff = (long)(bn0 + row) * 1024 + (K0) + kq; \
        cpasync16(dB,                         Bh + boff); \
        cpasync16(dB + (ST_B_L - ST_B_H) * 2, Bl + boff); \
    } } while (0)

#define GEMM_COMPUTE_STAGE(S) do { \
    const int soff = (S) * STAGE_E; \
    _Pragma("unroll") \
    for (int ks = 0; ks < 32; ks += 16) { \
        unsigned ah[4][4], al[4][4]; \
        _Pragma("unroll") \
        for (int mi = 0; mi < 4; mi++) { \
            const unsigned off = sbase + (soff + (wm * 64 + mi * 16 + (lane & 15)) * 40 + ks + akof) * 2; \
            ldsm4(off, ah[mi]); \
            ldsm4(off + ST_A_L * 2, al[mi]); \
        } \
        _Pragma("unroll") \
        for (int nip = 0; nip < 2; nip++) { \
            unsigned bh[4], bl[4]; \
            const unsigned off = sbase + (soff + ST_B_H + (wn * 32 + nip * 16 + brow) * 40 + ks + bkof) * 2; \
            ldsm4(off, bh); \
            ldsm4(off + (ST_B_L - ST_B_H) * 2, bl); \
            _Pragma("unroll") \
            for (int mi = 0; mi < 4; mi++) { \
                mma_bf16(acc[mi][2*nip],   ah[mi], bh); \
                mma_bf16(acc[mi][2*nip],   al[mi], bh); \
                mma_bf16(acc[mi][2*nip],   ah[mi], bl); \
                mma_bf16(acc[mi][2*nip+1], ah[mi], bh + 2); \
                mma_bf16(acc[mi][2*nip+1], al[mi], bh + 2); \
                mma_bf16(acc[mi][2*nip+1], ah[mi], bl + 2); \
            } \
        } \
    } } while (0)

#define GEMM_MAIN_LOOP() do { \
    GEMM_LOAD_STAGE(0, 0); \
    asm volatile("cp.async.commit_group;\n"); \
    _Pragma("unroll 1") \
    for (int kt = 0; kt < 32; kt++) { \
        asm volatile("cp.async.wait_group 0;\n"); \
        __syncthreads(); \
        if (kt + 1 < 32) { \
            GEMM_LOAD_STAGE((kt + 1) & 1, (kt + 1) * 32); \
            asm volatile("cp.async.commit_group;\n"); \
        } \
        GEMM_COMPUTE_STAGE(kt & 1); \
    } } while (0)

// ---------------------------------------------------------------------------
// Kernel 1: QKV projection + RoPE; Q pre-scaled by QSCALE_, K hi only, V hi/lo.
// ---------------------------------------------------------------------------
__global__ __launch_bounds__(256, 2) void qkv_mma_kernel(
    const float* __restrict__ cosT, const float* __restrict__ sinT)
{
    extern __shared__ __nv_bfloat16 smg[];
    const unsigned sbase = (unsigned)__cvta_generic_to_shared(smg);

    const int m0 = blockIdx.y * 128;
    const int n0 = blockIdx.x * 128;
    const int bn0 = n0;
    const int tid = threadIdx.x;
    const int warp = tid >> 5;
    const int lane = tid & 31;
    const int wm = warp & 1;
    const int wn = warp >> 1;
    const int lr  = lane >> 2;
    const int lc2 = (lane & 3) * 2;
    const int akof = (lane >> 4) * 8;
    const int brow = (lane & 7) + ((lane >> 4) & 1) * 8;
    const int bkof = ((lane >> 3) & 1) * 8;

    const __nv_bfloat16* Ah = g_Xh;
    const __nv_bfloat16* Al = g_Xl;
    const __nv_bfloat16* Bh = g_WTh;
    const __nv_bfloat16* Bl = g_WTl;

    float acc[4][4][4] = {};
    GEMM_MAIN_LOOP();

    const bool isq = (n0 < 1024);
    const bool isk = (n0 >= 1024 && n0 < 1280);

    #pragma unroll
    for (int mi = 0; mi < 4; mi++) {
        const int row0 = m0 + wm * 64 + mi * 16 + lr;
        #pragma unroll
        for (int ni = 0; ni < 4; ni++) {
            const int col = n0 + wn * 32 + ni * 8 + lc2;
            float e0 = acc[mi][ni][0], o0 = acc[mi][ni][1];
            float e1 = acc[mi][ni][2], o1 = acc[mi][ni][3];
            if (isq || isk) {
                const int pidx = (col & 63) >> 1;
                const int s0 = row0 & (S_ - 1);
                const int s1 = (row0 + 8) & (S_ - 1);
                float c, sn, re, im;
                c = cosT[s0 * 32 + pidx]; sn = sinT[s0 * 32 + pidx];
                re = e0 * c - o0 * sn; im = e0 * sn + o0 * c; e0 = re; o0 = im;
                c = cosT[s1 * 32 + pidx]; sn = sinT[s1 * 32 + pidx];
                re = e1 * c - o1 * sn; im = e1 * sn + o1 * c; e1 = re; o1 = im;
            }
            if (isq) {
                // fold softmax scale + log2(e) into Q
                e0 *= QSCALE_; o0 *= QSCALE_;
                e1 *= QSCALE_; o1 *= QSCALE_;
                unsigned h0, l0, h1, l1;
                split2(e0, o0, h0, l0);
                split2(e1, o1, h1, l1);
                *(unsigned*)&g_Qh[row0 * 1024 + col]       = h0;
                *(unsigned*)&g_Ql[row0 * 1024 + col]       = l0;
                *(unsigned*)&g_Qh[(row0 + 8) * 1024 + col] = h1;
                *(unsigned*)&g_Ql[(row0 + 8) * 1024 + col] = l1;
            } else if (isk) {
                const int cc = col - 1024;
                __nv_bfloat162 h0 = __floats2bfloat162_rn(e0, o0);
                __nv_bfloat162 h1 = __floats2bfloat162_rn(e1, o1);
                *(__nv_bfloat162*)&g_Kh[row0 * 256 + cc]       = h0;
                *(__nv_bfloat162*)&g_Kh[(row0 + 8) * 256 + cc] = h1;
            } else {
                const int cc = col - 1280;
                unsigned h0, l0, h1, l1;
                split2(e0, o0, h0, l0);
                split2(e1, o1, h1, l1);
                *(unsigned*)&g_Vh[row0 * 256 + cc]       = h0;
                *(unsigned*)&g_Vl[row0 * 256 + cc]       = l0;
                *(unsigned*)&g_Vh[(row0 + 8) * 256 + cc] = h1;
                *(unsigned*)&g_Vl[(row0 + 8) * 256 + cc] = l1;
            }
        }
    }
}

// ---------------------------------------------------------------------------
// Kernel 3: output projection
// ---------------------------------------------------------------------------
__global__ __launch_bounds__(256, 2) void out_mma_kernel(float* __restrict__ out)
{
    extern __shared__ __nv_bfloat16 smg[];
    const unsigned sbase = (unsigned)__cvta_generic_to_shared(smg);

    const int m0 = blockIdx.y * 128;
    const int n0 = blockIdx.x * 128;
    const int bn0 = n0;
    const int tid = threadIdx.x;
    const int warp = tid >> 5;
    const int lane = tid & 31;
    const int wm = warp & 1;
    const int wn = warp >> 1;
    const int lr  = lane >> 2;
    const int lc2 = (lane & 3) * 2;
    const int akof = (lane >> 4) * 8;
    const int brow = (lane & 7) + ((lane >> 4) & 1) * 8;
    const int bkof = ((lane >> 3) & 1) * 8;

    const __nv_bfloat16* Ah = g_Oh;
    const __nv_bfloat16* Al = g_Ol;
    const __nv_bfloat16* Bh = g_WoTh;
    const __nv_bfloat16* Bl = g_WoTl;

    float acc[4][4][4] = {};
    GEMM_MAIN_LOOP();

    #pragma unroll
    for (int mi = 0; mi < 4; mi++) {
        const int row0 = m0 + wm * 64 + mi * 16 + lr;
        #pragma unroll
        for (int ni = 0; ni < 4; ni++) {
            const int col = n0 + wn * 32 + ni * 8 + lc2;
            *(float2*)&out[row0 * 1024 + col] =
                make_float2(acc[mi][ni][0], acc[mi][ni][1]);
            *(float2*)&out[(row0 + 8) * 1024 + col] =
                make_float2(acc[mi][ni][2], acc[mi][ni][3]);
        }
    }
}

// ---------------------------------------------------------------------------
// Kernel 2: flash attention, causal, double-buffered, 2 CTAs/SM.
// QK^T 2-term; PV 3-term. Single sync per tile; ex2.approx (scale in Q).
// ---------------------------------------------------------------------------
constexpr int FQE = 128 * 72;
constexpr int FKE = 64 * 72;
constexpr int FSTG0 = 2 * FQE;
constexpr int FSTGSZ = 3 * FKE;
constexpr int FLASH_SMEM = (2 * FQE + 2 * FSTGSZ) * 2;  // 92160 B

#define FL_LOAD_TILE(ST, KV0) do { \
    const int sb = FSTG0 + (ST) * FSTGSZ; \
    _Pragma("unroll") \
    for (int it = 0; it < 2; it++) { \
        const int idx = tid + it * 256; \
        const int row = idx >> 3; \
        const int kq  = (idx & 7) * 8; \
        const long gk = (long)(b * S_ + (KV0) + row) * 256 + g * 64 + kq; \
        const unsigned dk = fbase + (sb + row * 72 + kq) * 2; \
        cpasync16(dk,               g_Kh + gk); \
        cpasync16(dk + FKE * 2,     g_Vh + gk); \
        cpasync16(dk + 2 * FKE * 2, g_Vl + gk); \
    } } while (0)

__global__ __launch_bounds__(256, 2) void flash_mma_kernel()
{
    extern __shared__ __nv_bfloat16 smf[];
    const unsigned fbase = (unsigned)__cvta_generic_to_shared(smf);

    const int qi = (int)gridDim.x - 1 - (int)blockIdx.x;
    const int h  = blockIdx.y;
    const int b  = blockIdx.z;
    const int g  = h >> 2;
    const int q0 = qi * 128;

    const int tid  = threadIdx.x;
    const int w    = tid >> 5;
    const int lane = tid & 31;
    const int lr   = lane >> 2;
    const int lc2  = (lane & 3) * 2;

    const int arow = w * 16 + (lane & 15);
    const int akof = (lane >> 4) * 8;
    const int brow = (lane & 7) + ((lane >> 4) & 1) * 8;
    const int bkof = ((lane >> 3) & 1) * 8;
    const int vrow = lane & 15;
    const int vcof = ((lane >> 4) & 1) * 8;

    #pragma unroll
    for (int it = 0; it < 4; it++) {
        const int idx = tid + it * 256;
        const int r  = idx >> 3;
        const int kq = (idx & 7) * 8;
        const long gq = (long)(b * S_ + q0 + r) * 1024 + h * 64 + kq;
        const unsigned dq = fbase + (r * 72 + kq) * 2;
        cpasync16(dq,           g_Qh + gq);
        cpasync16(dq + FQE * 2, g_Ql + gq);
    }
    FL_LOAD_TILE(0, 0);
    asm volatile("cp.async.commit_group;\n");

    float m0r = -INFINITY, m1r = -INFINITY;
    float l0r = 0.0f, l1r = 0.0f;
    float o[8][4] = {};

    const int ntiles = 2 * qi + 2;

    #pragma unroll 1
    for (int t = 0; t < ntiles; t++) {
        const int kv0 = t * 64;
        asm volatile("cp.async.wait_group 0;\n");
        __syncthreads();
        if (t + 1 < ntiles) {
            FL_LOAD_TILE((t + 1) & 1, (t + 1) * 64);
            asm volatile("cp.async.commit_group;\n");
        }

        if (kv0 <= q0 + w * 16 + 15) {
            const int sb = FSTG0 + (t & 1) * FSTGSZ;

            // --- S = Q K^T : 2-term bf16 (QhKh + QlKh); Q pre-scaled ---
            float s[8][4] = {};
            #pragma unroll
            for (int ks = 0; ks < 64; ks += 16) {
                unsigned ah[4], al[4];
                const unsigned aoff = fbase + (arow * 72 + ks + akof) * 2;
                ldsm4(aoff, ah);
                ldsm4(aoff + FQE * 2, al);
                #pragma unroll
                for (int nip = 0; nip < 4; nip++) {
                    unsigned bh[4];
                    const unsigned boff = fbase + (sb + (nip * 16 + brow) * 72 + ks + bkof) * 2;
                    ldsm4(boff, bh);
                    mma_bf16(s[2*nip],   ah, bh);
                    mma_bf16(s[2*nip],   al, bh);
                    mma_bf16(s[2*nip+1], ah, bh + 2);
                    mma_bf16(s[2*nip+1], al, bh + 2);
                }
            }

            const int r0g = q0 + w * 16 + lr;
            const int r1g = r0g + 8;
            const bool needMask = (kv0 + 63 > q0 + w * 16);

            float mlocA = -INFINITY, mlocB = -INFINITY;
            #pragma unroll
            for (int ni = 0; ni < 8; ni++) {
                #pragma unroll
                for (int j = 0; j < 2; j++) {
                    const int col = kv0 + ni * 8 + lc2 + j;
                    float v0 = s[ni][j];
                    float v1 = s[ni][2 + j];
                    if (needMask) {
                        if (col > r0g) v0 = -INFINITY;
                        if (col > r1g) v1 = -INFINITY;
                    }
                    s[ni][j]     = v0;
                    s[ni][2 + j] = v1;
                    mlocA = fmaxf(mlocA, v0);
                    mlocB = fmaxf(mlocB, v1);
                }
            }
            mlocA = fmaxf(mlocA, __shfl_xor_sync(0xffffffffu, mlocA, 1));
            mlocA = fmaxf(mlocA, __shfl_xor_sync(0xffffffffu, mlocA, 2));
            mlocB = fmaxf(mlocB, __shfl_xor_sync(0xffffffffu, mlocB, 1));
            mlocB = fmaxf(mlocB, __shfl_xor_sync(0xffffffffu, mlocB, 2));

            const float mnA = fmaxf(m0r, mlocA);
            const float mnB = fmaxf(m1r, mlocB);
            const float fA = ex2_fast(m0r - mnA);
            const float fB = ex2_fast(m1r - mnB);
            m0r = mnA; m1r = mnB;

            float lsA = 0.0f, lsB = 0.0f;
            #pragma unroll
            for (int ni = 0; ni < 8; ni++) {
                #pragma unroll
                for (int j = 0; j < 2; j++) {
                    float e0 = ex2_fast(s[ni][j]     - mnA);
                    float e1 = ex2_fast(s[ni][2 + j] - mnB);
                    s[ni][j]     = e0;
                    s[ni][2 + j] = e1;
                    lsA += e0;
                    lsB += e1;
                }
            }
            lsA += __shfl_xor_sync(0xffffffffu, lsA, 1);
            lsA += __shfl_xor_sync(0xffffffffu, lsA, 2);
            lsB += __shfl_xor_sync(0xffffffffu, lsB, 1);
            lsB += __shfl_xor_sync(0xffffffffu, lsB, 2);
            l0r = l0r * fA + lsA;
            l1r = l1r * fB + lsB;

            #pragma unroll
            for (int ni = 0; ni < 8; ni++) {
                o[ni][0] *= fA; o[ni][1] *= fA;
                o[ni][2] *= fB; o[ni][3] *= fB;
            }

            // --- O += P @ V : 3-term (PhVh + PlVh + PhVl) ---
            #pragma unroll
            for (int kc = 0; kc < 4; kc++) {
                unsigned pah[4], pal[4];
                #pragma unroll
                for (int half = 0; half < 2; half++) {
                    const int ni = 2 * kc + half;
                    split2(s[ni][0], s[ni][1], pah[2*half],     pal[2*half]);
                    split2(s[ni][2], s[ni][3], pah[2*half + 1], pal[2*half + 1]);
                }
                #pragma unroll
                for (int nip = 0; nip < 4; nip++) {
                    unsigned bvh[4], bvl[4];
                    const unsigned voff = fbase +
                        (sb + FKE + (kc * 16 + vrow) * 72 + nip * 16 + vcof) * 2;
                    ldsm4t(voff, bvh);
                    ldsm4t(voff + FKE * 2, bvl);
                    mma_bf16(o[2*nip],   pah, bvh);
                    mma_bf16(o[2*nip],   pal, bvh);
                    mma_bf16(o[2*nip],   pah, bvl);
                    mma_bf16(o[2*nip+1], pah, bvh + 2);
                    mma_bf16(o[2*nip+1], pal, bvh + 2);
                    mma_bf16(o[2*nip+1], pah, bvl + 2);
                }
            }
        }
    }

    const float invA = 1.0f / l0r;
    const float invB = 1.0f / l1r;
    const int row0 = b * S_ + q0 + w * 16 + lr;
    #pragma unroll
    for (int ni = 0; ni < 8; ni++) {
        const int col = h * 64 + ni * 8 + lc2;
        unsigned hA, lA, hB, lB;
        split2(o[ni][0] * invA, o[ni][1] * invA, hA, lA);
        split2(o[ni][2] * invB, o[ni][3] * invB, hB, lB);
        *(unsigned*)&g_Oh[row0 * 1024 + col]       = hA;
        *(unsigned*)&g_Ol[row0 * 1024 + col]       = lA;
        *(unsigned*)&g_Oh[(row0 + 8) * 1024 + col] = hB;
        *(unsigned*)&g_Ol[(row0 + 8) * 1024 + col] = lB;
    }
}

// ---------------------------------------------------------------------------
// inputs: 0=x 1=cos 2=sin 3=mask(unused) 4=wq 5=wk 6=wv 7=wo
// ---------------------------------------------------------------------------
extern "C" void kernel_launch(void* const* d_in, const int* in_sizes, int n_in,
                              void* d_out, int out_size)
{
    const float* x    = (const float*)d_in[0];
    const float* cosT = (const float*)d_in[1];
    const float* sinT = (const float*)d_in[2];
    const float* wq   = (const float*)d_in[4];
    const float* wk   = (const float*)d_in[5];
    const float* wv   = (const float*)d_in[6];
    const float* wo   = (const float*)d_in[7];
    float* out = (float*)d_out;

    cudaFuncSetAttribute(flash_mma_kernel,
                         cudaFuncAttributeMaxDynamicSharedMemorySize, FLASH_SMEM);
    cudaFuncSetAttribute(qkv_mma_kernel,
                         cudaFuncAttributeMaxDynamicSharedMemorySize, GEMM_SMEM_B);
    cudaFuncSetAttribute(out_mma_kernel,
                         cudaFuncAttributeMaxDynamicSharedMemorySize, GEMM_SMEM_B);

    convx_kernel<<<M_ * 1024 / (256 * 4), 256>>>(x);
    convw_all_kernel<<<dim3(80, 32), 256>>>(wq, wk, wv, wo);

    qkv_mma_kernel<<<dim3(12, 32), 256, GEMM_SMEM_B>>>(cosT, sinT);
    flash_mma_kernel<<<dim3(16, 16, 2), 256, FLASH_SMEM>>>();
    out_mma_kernel<<<dim3(8, 32), 256, GEMM_SMEM_B>>>(out);
}

// round 14
// speedup vs baseline: 3.2830x; 1.0254x over previous
#include <cuda_runtime.h>
#include <cuda_bf16.h>
#include <math.h>

constexpr int B_   = 2;
constexpr int S_   = 2048;
constexpr int M_   = B_ * S_;     // 4096
// softmax scale folded into Q: 0.125 * log2(e); flash uses exp2
constexpr float QSCALE_ = 0.125f * 1.44269504088896f;

// bf16 hi/lo operands (all intermediates)
__device__ __nv_bfloat16 g_Xh[M_ * 1024];
__device__ __nv_bfloat16 g_Xl[M_ * 1024];
__device__ __nv_bfloat16 g_WTh[1536 * 1024];   // [n][k] transposed qkv weights
__device__ __nv_bfloat16 g_WTl[1536 * 1024];
__device__ __nv_bfloat16 g_WoTh[1024 * 1024];  // [n][k] transposed wo
__device__ __nv_bfloat16 g_WoTl[1024 * 1024];
__device__ __nv_bfloat16 g_Qh[M_ * 1024];      // pre-scaled by QSCALE_
__device__ __nv_bfloat16 g_Ql[M_ * 1024];
__device__ __nv_bfloat16 g_Kh[M_ * 256];       // K hi only (2-term QK^T)
__device__ __nv_bfloat16 g_Vh[M_ * 256];
__device__ __nv_bfloat16 g_Vl[M_ * 256];
__device__ __nv_bfloat16 g_Oh[M_ * 1024];
__device__ __nv_bfloat16 g_Ol[M_ * 1024];

// ---------------------------------------------------------------------------
// helpers
// ---------------------------------------------------------------------------
__device__ __forceinline__ void mma_bf16(float* d, const unsigned* a, const unsigned* b) {
    asm volatile(
        "mma.sync.aligned.m16n8k16.row.col.f32.bf16.bf16.f32 "
        "{%0,%1,%2,%3},{%4,%5,%6,%7},{%8,%9},{%0,%1,%2,%3};\n"
        : "+f"(d[0]), "+f"(d[1]), "+f"(d[2]), "+f"(d[3])
        : "r"(a[0]), "r"(a[1]), "r"(a[2]), "r"(a[3]), "r"(b[0]), "r"(b[1]));
}
__device__ __forceinline__ void ldsm4(unsigned addr, unsigned* r) {
    asm volatile("ldmatrix.sync.aligned.m8n8.x4.shared.b16 {%0,%1,%2,%3}, [%4];"
                 : "=r"(r[0]), "=r"(r[1]), "=r"(r[2]), "=r"(r[3]) : "r"(addr));
}
__device__ __forceinline__ void ldsm4t(unsigned addr, unsigned* r) {
    asm volatile("ldmatrix.sync.aligned.m8n8.x4.trans.shared.b16 {%0,%1,%2,%3}, [%4];"
                 : "=r"(r[0]), "=r"(r[1]), "=r"(r[2]), "=r"(r[3]) : "r"(addr));
}
__device__ __forceinline__ void split2(float x0, float x1, unsigned& hi, unsigned& lo) {
    __nv_bfloat162 h = __floats2bfloat162_rn(x0, x1);
    float2 hf = __bfloat1622float2(h);
    __nv_bfloat162 l = __floats2bfloat162_rn(x0 - hf.x, x1 - hf.y);
    hi = *reinterpret_cast<unsigned*>(&h);
    lo = *reinterpret_cast<unsigned*>(&l);
}
__device__ __forceinline__ void cpasync16(unsigned dst, const void* src) {
    asm volatile("cp.async.cg.shared.global [%0], [%1], 16;\n" :: "r"(dst), "l"(src));
}
__device__ __forceinline__ float ex2_fast(float x) {
    float r;
    asm("ex2.approx.ftz.f32 %0, %1;" : "=f"(r) : "f"(x));
    return r;
}

// ---------------------------------------------------------------------------
// Prep kernel: convx (4096 blocks) + all weight transposes (2560 blocks)
// in ONE launch. Destinations resolved in device code (host-side __device__
// symbol addresses silently hit host memory via ATS on GB300).
// ---------------------------------------------------------------------------
__global__ __launch_bounds__(256) void prep_kernel(
    const float* __restrict__ x,
    const float* __restrict__ wq, const float* __restrict__ wk,
    const float* __restrict__ wv, const float* __restrict__ wo)
{
    const int gbx = blockIdx.x;
    if (gbx < 4096) {
        // convx: one float4 per thread
        const int idx = gbx * 256 + threadIdx.x;
        float4 v = ((const float4*)x)[idx];
        unsigned h01, l01, h23, l23;
        split2(v.x, v.y, h01, l01);
        split2(v.z, v.w, h23, l23);
        ((uint2*)g_Xh)[idx] = make_uint2(h01, h23);
        ((uint2*)g_Xl)[idx] = make_uint2(l01, l23);
        return;
    }
    // weight transpose region: flat id -> (bx, ky)
    const int id = gbx - 4096;      // 0..2559
    int bx = id >> 5;               // 0..79
    const int k0 = (id & 31) * 32;

    const float* w; int ncols, dstoff;
    __nv_bfloat16 *dsth, *dstl;
    if (bx < 32)      { w = wq; ncols = 1024; dstoff = 0;    dsth = g_WTh;  dstl = g_WTl; }
    else if (bx < 40) { w = wk; ncols = 256;  dstoff = 1024; dsth = g_WTh;  dstl = g_WTl;  bx -= 32; }
    else if (bx < 48) { w = wv; ncols = 256;  dstoff = 1280; dsth = g_WTh;  dstl = g_WTl;  bx -= 40; }
    else              { w = wo; ncols = 1024; dstoff = 0;    dsth = g_WoTh; dstl = g_WoTl; bx -= 48; }

    __shared__ float tile[32][33];
    const int n0 = bx * 32;
    const int tx = threadIdx.x & 31;
    const int ty = threadIdx.x >> 5;
    #pragma unroll
    for (int i = 0; i < 4; i++) {
        const int r = ty + i * 8;
        tile[r][tx] = w[(k0 + r) * ncols + n0 + tx];
    }
    __syncthreads();
    #pragma unroll
    for (int i = 0; i < 4; i++) {
        const int nr = ty + i * 8;
        const float v = tile[tx][nr];
        __nv_bfloat16 h = __float2bfloat16(v);
        const long o = (long)(dstoff + n0 + nr) * 1024 + k0 + tx;
        dsth[o] = h;
        dstl[o] = __float2bfloat16(v - __bfloat162float(h));
    }
}

// ---------------------------------------------------------------------------
// GEMM core: 128x128 tile, BK=32, double buffer, 8 warps, 2 CTAs/SM.
// SINGLE sync per iteration.
// ---------------------------------------------------------------------------
constexpr int ST_A_L = 128 * 40;
constexpr int ST_B_H = 2 * 128 * 40;
constexpr int ST_B_L = 3 * 128 * 40;
constexpr int STAGE_E = 4 * 128 * 40;
constexpr int GEMM_SMEM_B = 2 * STAGE_E * 2;   // 81920 bytes

#define GEMM_LOAD_STAGE(S, K0) do { \
    const int soff = (S) * STAGE_E; \
    _Pragma("unroll") \
    for (int it = 0; it < 2; it++) { \
        const int idx = tid + it * 256; \
        const int row = idx >> 2; \
        const int kq  = (idx & 3) * 8; \
        const unsigned dA = sbase + (soff + row * 40 + kq) * 2; \
        const long aoff = (long)(m0 + row) * 1024 + (K0) + kq; \
        cpasync16(dA,                Ah + aoff); \
        cpasync16(dA + ST_A_L * 2,   Al + aoff); \
        const unsigned dB = sbase + (soff + ST_B_H + row * 40 + kq) * 2; \
        const long boff = (long)(bn0 + row) * 1024 + (K0) + kq; \
        cpasync16(dB,                         Bh + boff); \
        cpasync16(dB + (ST_B_L - ST_B_H) * 2, Bl + boff); \
    } } while (0)

#define GEMM_COMPUTE_STAGE(S) do { \
    const int soff = (S) * STAGE_E; \
    _Pragma("unroll") \
    for (int ks = 0; ks < 32; ks += 16) { \
        unsigned ah[4][4], al[4][4]; \
        _Pragma("unroll") \
        for (int mi = 0; mi < 4; mi++) { \
            const unsigned off = sbase + (soff + (wm * 64 + mi * 16 + (lane & 15)) * 40 + ks + akof) * 2; \
            ldsm4(off, ah[mi]); \
            ldsm4(off + ST_A_L * 2, al[mi]); \
        } \
        _Pragma("unroll") \
        for (int nip = 0; nip < 2; nip++) { \
            unsigned bh[4], bl[4]; \
            const unsigned off = sbase + (soff + ST_B_H + (wn * 32 + nip * 16 + brow) * 40 + ks + bkof) * 2; \
            ldsm4(off, bh); \
            ldsm4(off + (ST_B_L - ST_B_H) * 2, bl); \
            _Pragma("unroll") \
            for (int mi = 0; mi < 4; mi++) { \
                mma_bf16(acc[mi][2*nip],   ah[mi], bh); \
                mma_bf16(acc[mi][2*nip],   al[mi], bh); \
                mma_bf16(acc[mi][2*nip],   ah[mi], bl); \
                mma_bf16(acc[mi][2*nip+1], ah[mi], bh + 2); \
                mma_bf16(acc[mi][2*nip+1], al[mi], bh + 2); \
                mma_bf16(acc[mi][2*nip+1], ah[mi], bl + 2); \
            } \
        } \
    } } while (0)

#define GEMM_MAIN_LOOP() do { \
    GEMM_LOAD_STAGE(0, 0); \
    asm volatile("cp.async.commit_group;\n"); \
    _Pragma("unroll 1") \
    for (int kt = 0; kt < 32; kt++) { \
        asm volatile("cp.async.wait_group 0;\n"); \
        __syncthreads(); \
        if (kt + 1 < 32) { \
            GEMM_LOAD_STAGE((kt + 1) & 1, (kt + 1) * 32); \
            asm volatile("cp.async.commit_group;\n"); \
        } \
        GEMM_COMPUTE_STAGE(kt & 1); \
    } } while (0)

// ---------------------------------------------------------------------------
// Kernel 1: QKV projection + RoPE; Q pre-scaled by QSCALE_, K hi only, V hi/lo.
// ---------------------------------------------------------------------------
__global__ __launch_bounds__(256, 2) void qkv_mma_kernel(
    const float* __restrict__ cosT, const float* __restrict__ sinT)
{
    extern __shared__ __nv_bfloat16 smg[];
    const unsigned sbase = (unsigned)__cvta_generic_to_shared(smg);

    const int m0 = blockIdx.y * 128;
    const int n0 = blockIdx.x * 128;
    const int bn0 = n0;
    const int tid = threadIdx.x;
    const int warp = tid >> 5;
    const int lane = tid & 31;
    const int wm = warp & 1;
    const int wn = warp >> 1;
    const int lr  = lane >> 2;
    const int lc2 = (lane & 3) * 2;
    const int akof = (lane >> 4) * 8;
    const int brow = (lane & 7) + ((lane >> 4) & 1) * 8;
    const int bkof = ((lane >> 3) & 1) * 8;

    const __nv_bfloat16* Ah = g_Xh;
    const __nv_bfloat16* Al = g_Xl;
    const __nv_bfloat16* Bh = g_WTh;
    const __nv_bfloat16* Bl = g_WTl;

    float acc[4][4][4] = {};
    GEMM_MAIN_LOOP();

    const bool isq = (n0 < 1024);
    const bool isk = (n0 >= 1024 && n0 < 1280);

    #pragma unroll
    for (int mi = 0; mi < 4; mi++) {
        const int row0 = m0 + wm * 64 + mi * 16 + lr;
        #pragma unroll
        for (int ni = 0; ni < 4; ni++) {
            const int col = n0 + wn * 32 + ni * 8 + lc2;
            float e0 = acc[mi][ni][0], o0 = acc[mi][ni][1];
            float e1 = acc[mi][ni][2], o1 = acc[mi][ni][3];
            if (isq || isk) {
                const int pidx = (col & 63) >> 1;
                const int s0 = row0 & (S_ - 1);
                const int s1 = (row0 + 8) & (S_ - 1);
                float c, sn, re, im;
                c = cosT[s0 * 32 + pidx]; sn = sinT[s0 * 32 + pidx];
                re = e0 * c - o0 * sn; im = e0 * sn + o0 * c; e0 = re; o0 = im;
                c = cosT[s1 * 32 + pidx]; sn = sinT[s1 * 32 + pidx];
                re = e1 * c - o1 * sn; im = e1 * sn + o1 * c; e1 = re; o1 = im;
            }
            if (isq) {
                e0 *= QSCALE_; o0 *= QSCALE_;
                e1 *= QSCALE_; o1 *= QSCALE_;
                unsigned h0, l0, h1, l1;
                split2(e0, o0, h0, l0);
                split2(e1, o1, h1, l1);
                *(unsigned*)&g_Qh[row0 * 1024 + col]       = h0;
                *(unsigned*)&g_Ql[row0 * 1024 + col]       = l0;
                *(unsigned*)&g_Qh[(row0 + 8) * 1024 + col] = h1;
                *(unsigned*)&g_Ql[(row0 + 8) * 1024 + col] = l1;
            } else if (isk) {
                const int cc = col - 1024;
                __nv_bfloat162 h0 = __floats2bfloat162_rn(e0, o0);
                __nv_bfloat162 h1 = __floats2bfloat162_rn(e1, o1);
                *(__nv_bfloat162*)&g_Kh[row0 * 256 + cc]       = h0;
                *(__nv_bfloat162*)&g_Kh[(row0 + 8) * 256 + cc] = h1;
            } else {
                const int cc = col - 1280;
                unsigned h0, l0, h1, l1;
                split2(e0, o0, h0, l0);
                split2(e1, o1, h1, l1);
                *(unsigned*)&g_Vh[row0 * 256 + cc]       = h0;
                *(unsigned*)&g_Vl[row0 * 256 + cc]       = l0;
                *(unsigned*)&g_Vh[(row0 + 8) * 256 + cc] = h1;
                *(unsigned*)&g_Vl[(row0 + 8) * 256 + cc] = l1;
            }
        }
    }
}

// ---------------------------------------------------------------------------
// Kernel 3: output projection
// ---------------------------------------------------------------------------
__global__ __launch_bounds__(256, 2) void out_mma_kernel(float* __restrict__ out)
{
    extern __shared__ __nv_bfloat16 smg[];
    const unsigned sbase = (unsigned)__cvta_generic_to_shared(smg);

    const int m0 = blockIdx.y * 128;
    const int n0 = blockIdx.x * 128;
    const int bn0 = n0;
    const int tid = threadIdx.x;
    const int warp = tid >> 5;
    const int lane = tid & 31;
    const int wm = warp & 1;
    const int wn = warp >> 1;
    const int lr  = lane >> 2;
    const int lc2 = (lane & 3) * 2;
    const int akof = (lane >> 4) * 8;
    const int brow = (lane & 7) + ((lane >> 4) & 1) * 8;
    const int bkof = ((lane >> 3) & 1) * 8;

    const __nv_bfloat16* Ah = g_Oh;
    const __nv_bfloat16* Al = g_Ol;
    const __nv_bfloat16* Bh = g_WoTh;
    const __nv_bfloat16* Bl = g_WoTl;

    float acc[4][4][4] = {};
    GEMM_MAIN_LOOP();

    #pragma unroll
    for (int mi = 0; mi < 4; mi++) {
        const int row0 = m0 + wm * 64 + mi * 16 + lr;
        #pragma unroll
        for (int ni = 0; ni < 4; ni++) {
            const int col = n0 + wn * 32 + ni * 8 + lc2;
            *(float2*)&out[row0 * 1024 + col] =
                make_float2(acc[mi][ni][0], acc[mi][ni][1]);
            *(float2*)&out[(row0 + 8) * 1024 + col] =
                make_float2(acc[mi][ni][2], acc[mi][ni][3]);
        }
    }
}

// ---------------------------------------------------------------------------
// Kernel 2: flash attention, causal, 2 CTAs/SM. QK^T 2-term, PV 3-term,
// ex2.approx. K and V in SEPARATE cp.async groups: wait K before QK, wait V
// only after softmax -> V loads hide under QK+softmax, K under PV.
// ---------------------------------------------------------------------------
constexpr int FQE = 128 * 72;
constexpr int FKE = 64 * 72;
constexpr int FSTG0 = 2 * FQE;
constexpr int FSTGSZ = 3 * FKE;    // Kh | Vh | Vl
constexpr int FLASH_SMEM = (2 * FQE + 2 * FSTGSZ) * 2;  // 92160 B

#define FL_LOAD_K(ST, KV0) do { \
    const int sb = FSTG0 + (ST) * FSTGSZ; \
    _Pragma("unroll") \
    for (int it = 0; it < 2; it++) { \
        const int idx = tid + it * 256; \
        const int row = idx >> 3; \
        const int kq  = (idx & 7) * 8; \
        const long gk = (long)(b * S_ + (KV0) + row) * 256 + g * 64 + kq; \
        cpasync16(fbase + (sb + row * 72 + kq) * 2, g_Kh + gk); \
    } } while (0)

#define FL_LOAD_V(ST, KV0) do { \
    const int sb = FSTG0 + (ST) * FSTGSZ + FKE; \
    _Pragma("unroll") \
    for (int it = 0; it < 2; it++) { \
        const int idx = tid + it * 256; \
        const int row = idx >> 3; \
        const int kq  = (idx & 7) * 8; \
        const long gk = (long)(b * S_ + (KV0) + row) * 256 + g * 64 + kq; \
        const unsigned dv = fbase + (sb + row * 72 + kq) * 2; \
        cpasync16(dv,           g_Vh + gk); \
        cpasync16(dv + FKE * 2, g_Vl + gk); \
    } } while (0)

__global__ __launch_bounds__(256, 2) void flash_mma_kernel()
{
    extern __shared__ __nv_bfloat16 smf[];
    const unsigned fbase = (unsigned)__cvta_generic_to_shared(smf);

    const int qi = (int)gridDim.x - 1 - (int)blockIdx.x;
    const int h  = blockIdx.y;
    const int b  = blockIdx.z;
    const int g  = h >> 2;
    const int q0 = qi * 128;

    const int tid  = threadIdx.x;
    const int w    = tid >> 5;
    const int lane = tid & 31;
    const int lr   = lane >> 2;
    const int lc2  = (lane & 3) * 2;

    const int arow = w * 16 + (lane & 15);
    const int akof = (lane >> 4) * 8;
    const int brow = (lane & 7) + ((lane >> 4) & 1) * 8;
    const int bkof = ((lane >> 3) & 1) * 8;
    const int vrow = lane & 15;
    const int vcof = ((lane >> 4) & 1) * 8;

    // Q tile (grouped with K0's group)
    #pragma unroll
    for (int it = 0; it < 4; it++) {
        const int idx = tid + it * 256;
        const int r  = idx >> 3;
        const int kq = (idx & 7) * 8;
        const long gq = (long)(b * S_ + q0 + r) * 1024 + h * 64 + kq;
        const unsigned dq = fbase + (r * 72 + kq) * 2;
        cpasync16(dq,           g_Qh + gq);
        cpasync16(dq + FQE * 2, g_Ql + gq);
    }
    // prologue: commit K0 (incl Q), then V0 — keeps the invariant that at
    // the top of each iteration the outstanding groups are [K(t), V(t)].
    FL_LOAD_K(0, 0);
    asm volatile("cp.async.commit_group;\n");
    FL_LOAD_V(0, 0);
    asm volatile("cp.async.commit_group;\n");

    float m0r = -INFINITY, m1r = -INFINITY;
    float l0r = 0.0f, l1r = 0.0f;
    float o[8][4] = {};

    const int ntiles = 2 * qi + 2;

    #pragma unroll 1
    for (int t = 0; t < ntiles; t++) {
        const int kv0 = t * 64;
        const bool more = (t + 1 < ntiles);
        // outstanding: [K(t), V(t)] -> wait K(t) (V(t) may still fly)
        asm volatile("cp.async.wait_group 1;\n");
        __syncthreads();
        if (more) {                       // issue K(t+1): overlaps QK+softmax+PV
            FL_LOAD_K((t + 1) & 1, (t + 1) * 64);
            asm volatile("cp.async.commit_group;\n");
        }

        const bool active = (kv0 <= q0 + w * 16 + 15);
        const int sb = FSTG0 + (t & 1) * FSTGSZ;
        float s[8][4] = {};

        if (active) {
            // --- S = Q K^T : 2-term bf16 (QhKh + QlKh); Q pre-scaled ---
            #pragma unroll
            for (int ks = 0; ks < 64; ks += 16) {
                unsigned ah[4], al[4];
                const unsigned aoff = fbase + (arow * 72 + ks + akof) * 2;
                ldsm4(aoff, ah);
                ldsm4(aoff + FQE * 2, al);
                #pragma unroll
                for (int nip = 0; nip < 4; nip++) {
                    unsigned bh[4];
                    const unsigned boff = fbase + (sb + (nip * 16 + brow) * 72 + ks + bkof) * 2;
                    ldsm4(boff, bh);
                    mma_bf16(s[2*nip],   ah, bh);
                    mma_bf16(s[2*nip],   al, bh);
                    mma_bf16(s[2*nip+1], ah, bh + 2);
                    mma_bf16(s[2*nip+1], al, bh + 2);
                }
            }

            const int r0g = q0 + w * 16 + lr;
            const int r1g = r0g + 8;
            const bool needMask = (kv0 + 63 > q0 + w * 16);

            float mlocA = -INFINITY, mlocB = -INFINITY;
            #pragma unroll
            for (int ni = 0; ni < 8; ni++) {
                #pragma unroll
                for (int j = 0; j < 2; j++) {
                    const int col = kv0 + ni * 8 + lc2 + j;
                    float v0 = s[ni][j];
                    float v1 = s[ni][2 + j];
                    if (needMask) {
                        if (col > r0g) v0 = -INFINITY;
                        if (col > r1g) v1 = -INFINITY;
                    }
                    s[ni][j]     = v0;
                    s[ni][2 + j] = v1;
                    mlocA = fmaxf(mlocA, v0);
                    mlocB = fmaxf(mlocB, v1);
                }
            }
            mlocA = fmaxf(mlocA, __shfl_xor_sync(0xffffffffu, mlocA, 1));
            mlocA = fmaxf(mlocA, __shfl_xor_sync(0xffffffffu, mlocA, 2));
            mlocB = fmaxf(mlocB, __shfl_xor_sync(0xffffffffu, mlocB, 1));
            mlocB = fmaxf(mlocB, __shfl_xor_sync(0xffffffffu, mlocB, 2));

            const float mnA = fmaxf(m0r, mlocA);
            const float mnB = fmaxf(m1r, mlocB);
            const float fA = ex2_fast(m0r - mnA);
            const float fB = ex2_fast(m1r - mnB);
            m0r = mnA; m1r = mnB;

            float lsA = 0.0f, lsB = 0.0f;
            #pragma unroll
            for (int ni = 0; ni < 8; ni++) {
                #pragma unroll
                for (int j = 0; j < 2; j++) {
                    float e0 = ex2_fast(s[ni][j]     - mnA);
                    float e1 = ex2_fast(s[ni][2 + j] - mnB);
                    s[ni][j]     = e0;
                    s[ni][2 + j] = e1;
                    lsA += e0;
                    lsB += e1;
                }
            }
            lsA += __shfl_xor_sync(0xffffffffu, lsA, 1);
            lsA += __shfl_xor_sync(0xffffffffu, lsA, 2);
            lsB += __shfl_xor_sync(0xffffffffu, lsB, 1);
            lsB += __shfl_xor_sync(0xffffffffu, lsB, 2);
            l0r = l0r * fA + lsA;
            l1r = l1r * fB + lsB;

            #pragma unroll
            for (int ni = 0; ni < 8; ni++) {
                o[ni][0] *= fA; o[ni][1] *= fA;
                o[ni][2] *= fB; o[ni][3] *= fB;
            }
        }

        // outstanding: [V(t), K(t+1)] -> wait V(t) (K(t+1) may still fly)
        asm volatile("cp.async.wait_group 1;\n");
        if (more) {                       // issue V(t+1): overlaps PV(t)
            FL_LOAD_V((t + 1) & 1, (t + 1) * 64);
            asm volatile("cp.async.commit_group;\n");
        }

        if (active) {
            // --- O += P @ V : 3-term (PhVh + PlVh + PhVl) ---
            #pragma unroll
            for (int kc = 0; kc < 4; kc++) {
                unsigned pah[4], pal[4];
                #pragma unroll
                for (int half = 0; half < 2; half++) {
                    const int ni = 2 * kc + half;
                    split2(s[ni][0], s[ni][1], pah[2*half],     pal[2*half]);
                    split2(s[ni][2], s[ni][3], pah[2*half + 1], pal[2*half + 1]);
                }
                #pragma unroll
                for (int nip = 0; nip < 4; nip++) {
                    unsigned bvh[4], bvl[4];
                    const unsigned voff = fbase +
                        (sb + FKE + (kc * 16 + vrow) * 72 + nip * 16 + vcof) * 2;
                    ldsm4t(voff, bvh);
                    ldsm4t(voff + FKE * 2, bvl);
                    mma_bf16(o[2*nip],   pah, bvh);
                    mma_bf16(o[2*nip],   pal, bvh);
                    mma_bf16(o[2*nip],   pah, bvl);
                    mma_bf16(o[2*nip+1], pah, bvh + 2);
                    mma_bf16(o[2*nip+1], pal, bvh + 2);
                    mma_bf16(o[2*nip+1], pah, bvl + 2);
                }
            }
        }
    }

    const float invA = 1.0f / l0r;
    const float invB = 1.0f / l1r;
    const int row0 = b * S_ + q0 + w * 16 + lr;
    #pragma unroll
    for (int ni = 0; ni < 8; ni++) {
        const int col = h * 64 + ni * 8 + lc2;
        unsigned hA, lA, hB, lB;
        split2(o[ni][0] * invA, o[ni][1] * invA, hA, lA);
        split2(o[ni][2] * invB, o[ni][3] * invB, hB, lB);
        *(unsigned*)&g_Oh[row0 * 1024 + col]       = hA;
        *(unsigned*)&g_Ol[row0 * 1024 + col]       = lA;
        *(unsigned*)&g_Oh[(row0 + 8) * 1024 + col] = hB;
        *(unsigned*)&g_Ol[(row0 + 8) * 1024 + col] = lB;
    }
}

// ---------------------------------------------------------------------------
// inputs: 0=x 1=cos 2=sin 3=mask(unused) 4=wq 5=wk 6=wv 7=wo
// ---------------------------------------------------------------------------
extern "C" void kernel_launch(void* const* d_in, const int* in_sizes, int n_in,
                              void* d_out, int out_size)
{
    const float* x    = (const float*)d_in[0];
    const float* cosT = (const float*)d_in[1];
    const float* sinT = (const float*)d_in[2];
    const float* wq   = (const float*)d_in[4];
    const float* wk   = (const float*)d_in[5];
    const float* wv   = (const float*)d_in[6];
    const float* wo   = (const float*)d_in[7];
    float* out = (float*)d_out;

    cudaFuncSetAttribute(flash_mma_kernel,
                         cudaFuncAttributeMaxDynamicSharedMemorySize, FLASH_SMEM);
    cudaFuncSetAttribute(qkv_mma_kernel,
                         cudaFuncAttributeMaxDynamicSharedMemorySize, GEMM_SMEM_B);
    cudaFuncSetAttribute(out_mma_kernel,
                         cudaFuncAttributeMaxDynamicSharedMemorySize, GEMM_SMEM_B);

    prep_kernel<<<4096 + 2560, 256>>>(x, wq, wk, wv, wo);
    qkv_mma_kernel<<<dim3(12, 32), 256, GEMM_SMEM_B>>>(cosT, sinT);
    flash_mma_kernel<<<dim3(16, 16, 2), 256, FLASH_SMEM>>>();
    out_mma_kernel<<<dim3(8, 32), 256, GEMM_SMEM_B>>>(out);
}